// round 9
// baseline (speedup 1.0000x reference)
#include <cuda_runtime.h>
#include <cuda_bf16.h>
#include <cstdint>

#define NMAX 100000
#define EMAX 3200000
#define EA_SCALE 32767.0f
#define EA_INV (1.0f / 32767.0f)

// Scratch (device globals: allocation is forbidden).
__device__ float g_deg[NMAX];
__device__ float g_dis[NMAX];
__device__ float g_xs[NMAX];            // dis * x (layer-1 scaled input)
__device__ int   g_cnt[NMAX];
__device__ int   g_rs[NMAX + 1];
__device__ int   g_cur[NMAX];
__device__ unsigned long long g_sstate[128];   // lookback scan state
__device__ unsigned g_edges[EMAX];      // packed (src<<15)|q15(ea), dst-sorted
__device__ float g_bufA[NMAX * 64];
__device__ float g_bufB[NMAX * 64];
__device__ float g_t1[NMAX * 64];
__device__ float g_t1s[NMAX];           // dis * t1 (layer-1 chain)
__device__ float g_t2[NMAX * 64];
__device__ __nv_bfloat16 g_xb[NMAX * 32];   // bf16 shadow (dis-scaled)
__device__ __nv_bfloat16 g_tb[NMAX * 32];   // bf16 shadow of t1 (dis-scaled)

static inline int cdiv(long long a, int b) { return (int)((a + b - 1) / b); }

__device__ __forceinline__ void decode_edge(unsigned rec, int& s, float& w) {
    s = (int)(rec >> 15);
    w = (float)(rec & 0x7FFFu) * EA_INV;
}

// ---------------------------------------------------------------------------
// fused zero of deg/cnt + scan state
// ---------------------------------------------------------------------------
__global__ void zero_build_k(float* deg, int* cnt, unsigned long long* sstate, int n) {
    int i = blockIdx.x * blockDim.x + threadIdx.x;
    if (i < n) { deg[i] = 0.f; cnt[i] = 0; }
    if (i < 128) sstate[i] = 0ULL;
}

// ---------------------------------------------------------------------------
// deg[src[e]] += ea[e];  cnt[dst[e]] += 1   — 4 edges per thread
// ---------------------------------------------------------------------------
__global__ void deg_hist_k(const int* __restrict__ src, const int* __restrict__ dst,
                           const float* __restrict__ ea,
                           float* __restrict__ deg, int* __restrict__ cnt, int E) {
    int base = (blockIdx.x * blockDim.x + threadIdx.x) * 4;
    if (base + 3 < E) {
        int4 s = *reinterpret_cast<const int4*>(src + base);
        int4 d = *reinterpret_cast<const int4*>(dst + base);
        float4 w = *reinterpret_cast<const float4*>(ea + base);
        atomicAdd(&deg[s.x], w.x);
        atomicAdd(&deg[s.y], w.y);
        atomicAdd(&deg[s.z], w.z);
        atomicAdd(&deg[s.w], w.w);
        atomicAdd(&cnt[d.x], 1);
        atomicAdd(&cnt[d.y], 1);
        atomicAdd(&cnt[d.z], 1);
        atomicAdd(&cnt[d.w], 1);
    } else {
        for (int e = base; e < E; e++) {
            atomicAdd(&deg[src[e]], ea[e]);
            atomicAdd(&cnt[dst[e]], 1);
        }
    }
}

// ---------------------------------------------------------------------------
// dis[i] = deg>0 ? rsqrt(deg) : 0 ; xs[i] = dis[i]*x[i]
// ---------------------------------------------------------------------------
__global__ void dis_k(const float* __restrict__ deg, const float* __restrict__ x,
                      float* __restrict__ dis, float* __restrict__ xs, int n) {
    int i = blockIdx.x * blockDim.x + threadIdx.x;
    if (i >= n) return;
    float d = deg[i];
    float r = d > 0.f ? rsqrtf(d) : 0.f;
    dis[i] = r;
    xs[i] = r * x[i];
}

// ---------------------------------------------------------------------------
// Single-pass decoupled-lookback exclusive scan of cnt -> rs, cur.
// ---------------------------------------------------------------------------
#define SCAN_TPB 256
#define SCAN_ELEMS 1024

__global__ void scan_lookback_k(const int* __restrict__ cnt,
                                unsigned long long* __restrict__ sstate,
                                int* __restrict__ rs, int* __restrict__ cur, int n) {
    int b = blockIdx.x;
    int base = b * SCAN_ELEMS + threadIdx.x * 4;
    int c0 = 0, c1 = 0, c2 = 0, c3 = 0;
    if (base + 3 < n) {
        int4 v = *reinterpret_cast<const int4*>(cnt + base);
        c0 = v.x; c1 = v.y; c2 = v.z; c3 = v.w;
    } else {
        if (base + 0 < n) c0 = cnt[base + 0];
        if (base + 1 < n) c1 = cnt[base + 1];
        if (base + 2 < n) c2 = cnt[base + 2];
        if (base + 3 < n) c3 = cnt[base + 3];
    }
    int ts = c0 + c1 + c2 + c3;
    int lane = threadIdx.x & 31, wid = threadIdx.x >> 5;
    int inc = ts;
#pragma unroll
    for (int o = 1; o < 32; o <<= 1) {
        int v = __shfl_up_sync(0xffffffffu, inc, o);
        if (lane >= o) inc += v;
    }
    __shared__ int wsum[SCAN_TPB / 32];
    __shared__ int woff[SCAN_TPB / 32];
    __shared__ int s_base;
    __shared__ int s_total;
    if (lane == 31) wsum[wid] = inc;
    __syncthreads();
    if (threadIdx.x == 0) {
        int r = 0;
#pragma unroll
        for (int w = 0; w < SCAN_TPB / 32; w++) { woff[w] = r; r += wsum[w]; }
        s_total = r;
        atomicExch(&sstate[b], (1ULL << 62) | (unsigned)r);
        int excl = 0;
        for (int p = b - 1; p >= 0; ) {
            unsigned long long s;
            do { s = atomicAdd(&sstate[p], 0ULL); } while ((s >> 62) == 0);
            excl += (int)(unsigned)s;
            if ((s >> 62) == 2ULL) break;
            p--;
        }
        atomicExch(&sstate[b], (2ULL << 62) | (unsigned)(excl + r));
        s_base = excl;
    }
    __syncthreads();
    int r = s_base + (inc - ts) + woff[wid];
    if (base + 0 < n) { rs[base + 0] = r; cur[base + 0] = r; r += c0; }
    if (base + 1 < n) { rs[base + 1] = r; cur[base + 1] = r; r += c1; }
    if (base + 2 < n) { rs[base + 2] = r; cur[base + 2] = r; r += c2; }
    if (base + 3 < n) { rs[base + 3] = r; cur[base + 3] = r; r += c3; }
    if (b == gridDim.x - 1 && threadIdx.x == 0) rs[n] = s_base + s_total;
}

// ---------------------------------------------------------------------------
// scatter: 4 edges per thread; 4-byte packed records
// ---------------------------------------------------------------------------
__global__ void scatter_k(const int* __restrict__ src, const int* __restrict__ dst,
                          const float* __restrict__ ea,
                          int* __restrict__ cur, unsigned* __restrict__ ed, int E) {
    int base = (blockIdx.x * blockDim.x + threadIdx.x) * 4;
    if (base + 3 < E) {
        int4 s = *reinterpret_cast<const int4*>(src + base);
        int4 d = *reinterpret_cast<const int4*>(dst + base);
        float4 w = *reinterpret_cast<const float4*>(ea + base);
        int p0 = atomicAdd(&cur[d.x], 1);
        int p1 = atomicAdd(&cur[d.y], 1);
        int p2 = atomicAdd(&cur[d.z], 1);
        int p3 = atomicAdd(&cur[d.w], 1);
        ed[p0] = ((unsigned)s.x << 15) | (unsigned)__float2int_rn(w.x * EA_SCALE);
        ed[p1] = ((unsigned)s.y << 15) | (unsigned)__float2int_rn(w.y * EA_SCALE);
        ed[p2] = ((unsigned)s.z << 15) | (unsigned)__float2int_rn(w.z * EA_SCALE);
        ed[p3] = ((unsigned)s.w << 15) | (unsigned)__float2int_rn(w.w * EA_SCALE);
    } else {
        for (int e = base; e < E; e++) {
            int slot = atomicAdd(&cur[dst[e]], 1);
            ed[slot] = ((unsigned)src[e] << 15)
                     | (unsigned)__float2int_rn(ea[e] * EA_SCALE);
        }
    }
}

// ---------------------------------------------------------------------------
// C == 1 props.
// ---------------------------------------------------------------------------
template <bool WRITE_S>
__global__ void prop_c1(const float* __restrict__ xs, const float* __restrict__ dis,
                        const unsigned* __restrict__ ed, const int* __restrict__ rs,
                        float* __restrict__ out, float* __restrict__ outs, int N) {
    int warp = (blockIdx.x * blockDim.x + threadIdx.x) >> 5;
    int lane = threadIdx.x & 31;
    if (warp >= N) return;
    int beg = rs[warp], end = rs[warp + 1];
    float acc = 0.f;
    for (int j = beg + lane; j < end; j += 32) {
        int s; float w; decode_edge(ed[j], s, w);
        acc += w * __ldg(xs + s);
    }
#pragma unroll
    for (int off = 16; off > 0; off >>= 1)
        acc += __shfl_down_sync(0xffffffffu, acc, off);
    if (lane == 0) {
        float di = dis[warp];
        float r = -di * acc;
        out[warp] = r;
        if (WRITE_S) outs[warp] = di * r;
    }
}

// ---------------------------------------------------------------------------
// bf16 CSR gather, C == 16: grp = lane>>3 (4 edge slots), sub = lane&7.
// ---------------------------------------------------------------------------
template <bool WRITE_B>
__global__ void prop_c16_bf16(const __nv_bfloat16* __restrict__ xb,
                              const float* __restrict__ dis,
                              const unsigned* __restrict__ ed, const int* __restrict__ rs,
                              float* __restrict__ out, __nv_bfloat16* __restrict__ outb,
                              int N) {
    int warp = (blockIdx.x * blockDim.x + threadIdx.x) >> 5;
    int lane = threadIdx.x & 31;
    if (warp >= N) return;
    int grp = lane >> 3;
    int sub = lane & 7;
    int beg = rs[warp], end = rs[warp + 1];
    float ax = 0.f, ay = 0.f;
    int j = beg;
    for (; j + 16 <= end; j += 16) {
        unsigned e[4];
#pragma unroll
        for (int k = 0; k < 4; k++) e[k] = ed[j + k * 4 + grp];
        float2 f[4];
#pragma unroll
        for (int k = 0; k < 4; k++) {
            __nv_bfloat162 v = *reinterpret_cast<const __nv_bfloat162*>(
                xb + (size_t)(e[k] >> 15) * 16 + sub * 2);
            f[k] = __bfloat1622float2(v);
        }
#pragma unroll
        for (int k = 0; k < 4; k++) {
            float w = (float)(e[k] & 0x7FFFu) * EA_INV;
            ax = fmaf(w, f[k].x, ax);
            ay = fmaf(w, f[k].y, ay);
        }
    }
    for (; j < end; j += 4) {
        int idx = j + grp;
        if (idx < end) {
            int s; float w; decode_edge(ed[idx], s, w);
            __nv_bfloat162 v = *reinterpret_cast<const __nv_bfloat162*>(
                xb + (size_t)s * 16 + sub * 2);
            float2 f = __bfloat1622float2(v);
            ax = fmaf(w, f.x, ax); ay = fmaf(w, f.y, ay);
        }
    }
    ax += __shfl_xor_sync(0xffffffffu, ax, 8);
    ay += __shfl_xor_sync(0xffffffffu, ay, 8);
    ax += __shfl_xor_sync(0xffffffffu, ax, 16);
    ay += __shfl_xor_sync(0xffffffffu, ay, 16);
    if (lane < 8) {
        float di = dis[warp];
        float2 r; r.x = -di * ax; r.y = -di * ay;
        *reinterpret_cast<float2*>(out + (size_t)warp * 16 + sub * 2) = r;
        if (WRITE_B) {
            float2 s; s.x = di * r.x; s.y = di * r.y;
            __nv_bfloat162 b = __float22bfloat162_rn(s);
            *reinterpret_cast<__nv_bfloat162*>(outb + (size_t)warp * 16 + sub * 2) = b;
        }
    }
}

// ---------------------------------------------------------------------------
// bf16 CSR gather, C == 32: grp = lane>>4 (2 edge slots), sub = lane&15.
// ---------------------------------------------------------------------------
template <bool WRITE_B>
__global__ void prop_c32_bf16(const __nv_bfloat16* __restrict__ xb,
                              const float* __restrict__ dis,
                              const unsigned* __restrict__ ed, const int* __restrict__ rs,
                              float* __restrict__ out, __nv_bfloat16* __restrict__ outb,
                              int N) {
    int warp = (blockIdx.x * blockDim.x + threadIdx.x) >> 5;
    int lane = threadIdx.x & 31;
    if (warp >= N) return;
    int grp = lane >> 4;
    int sub = lane & 15;
    int beg = rs[warp], end = rs[warp + 1];
    float ax = 0.f, ay = 0.f;
    int j = beg;
    for (; j + 16 <= end; j += 16) {
        unsigned e[8];
#pragma unroll
        for (int k = 0; k < 8; k++) e[k] = ed[j + k * 2 + grp];
        float2 f[8];
#pragma unroll
        for (int k = 0; k < 8; k++) {
            __nv_bfloat162 v = *reinterpret_cast<const __nv_bfloat162*>(
                xb + (size_t)(e[k] >> 15) * 32 + sub * 2);
            f[k] = __bfloat1622float2(v);
        }
#pragma unroll
        for (int k = 0; k < 8; k++) {
            float w = (float)(e[k] & 0x7FFFu) * EA_INV;
            ax = fmaf(w, f[k].x, ax);
            ay = fmaf(w, f[k].y, ay);
        }
    }
    for (; j < end; j += 2) {
        int idx = j + grp;
        if (idx < end) {
            int s; float w; decode_edge(ed[idx], s, w);
            __nv_bfloat162 v = *reinterpret_cast<const __nv_bfloat162*>(
                xb + (size_t)s * 32 + sub * 2);
            float2 f = __bfloat1622float2(v);
            ax = fmaf(w, f.x, ax); ay = fmaf(w, f.y, ay);
        }
    }
    ax += __shfl_xor_sync(0xffffffffu, ax, 16);
    ay += __shfl_xor_sync(0xffffffffu, ay, 16);
    if (lane < 16) {
        float di = dis[warp];
        float2 r; r.x = -di * ax; r.y = -di * ay;
        *reinterpret_cast<float2*>(out + (size_t)warp * 32 + sub * 2) = r;
        if (WRITE_B) {
            float2 s; s.x = di * r.x; s.y = di * r.y;
            __nv_bfloat162 b = __float22bfloat162_rn(s);
            *reinterpret_cast<__nv_bfloat162*>(outb + (size_t)warp * 32 + sub * 2) = b;
        }
    }
}

// ---------------------------------------------------------------------------
// C == 4 prop of zpack (dis-scaled [z1|z2]).
// ---------------------------------------------------------------------------
__global__ void prop_csr_c4(const float* __restrict__ zs, const float* __restrict__ dis,
                            const unsigned* __restrict__ ed, const int* __restrict__ rs,
                            float* __restrict__ out, int N) {
    int warp = (blockIdx.x * blockDim.x + threadIdx.x) >> 5;
    int lane = threadIdx.x & 31;
    if (warp >= N) return;
    int k = lane >> 2;
    int c = lane & 3;
    int beg = rs[warp], end = rs[warp + 1];
    float acc = 0.f;
    for (int j = beg + k; j < end; j += 8) {
        int s; float w; decode_edge(ed[j], s, w);
        acc = fmaf(w, __ldg(zs + (size_t)s * 4 + c), acc);
    }
#pragma unroll
    for (int off = 16; off >= 4; off >>= 1)
        acc += __shfl_down_sync(0xffffffffu, acc, off);
    if (lane < 4) {
        float di = dis[warp];
        float r = -di * acc;
        out[(size_t)warp * 4 + c] = (c < 2) ? r : di * r;
    }
}

// ---------------------------------------------------------------------------
// Final tail: y = part + t4[:,0:2] + 2 * (-dis[d] * sum w * t4[s, 2+c])
// ---------------------------------------------------------------------------
__global__ void prop2_final_k(const float* __restrict__ t4, const float* __restrict__ part,
                              const float* __restrict__ dis,
                              const unsigned* __restrict__ ed, const int* __restrict__ rs,
                              float* __restrict__ y, int N) {
    int warp = (blockIdx.x * blockDim.x + threadIdx.x) >> 5;
    int lane = threadIdx.x & 31;
    if (warp >= N) return;
    int k = lane >> 1;
    int c = lane & 1;
    int beg = rs[warp], end = rs[warp + 1];
    float acc = 0.f;
    for (int j = beg + k; j < end; j += 16) {
        int s; float w; decode_edge(ed[j], s, w);
        acc = fmaf(w, __ldg(t4 + (size_t)s * 4 + 2 + c), acc);
    }
#pragma unroll
    for (int off = 16; off >= 2; off >>= 1)
        acc += __shfl_down_sync(0xffffffffu, acc, off);
    if (lane < 2) {
        float w = -dis[warp] * acc;
        y[(size_t)warp * 2 + c] = part[(size_t)warp * 2 + c]
                                + t4[(size_t)warp * 4 + c] + 2.f * w;
    }
}

// ---------------------------------------------------------------------------
// Layer-4 head GEMM: part = h@W0 - h@W2 ; zpack = dis[n]*[h@W1 | h@W2]
// ---------------------------------------------------------------------------
__global__ void gemm_head_64_2(const float* __restrict__ h, const float* __restrict__ dis,
                               const float* __restrict__ W,
                               float* __restrict__ part, float* __restrict__ zpack, int n) {
    __shared__ float sW[6 * 64];
    for (int i = threadIdx.x; i < 384; i += blockDim.x) {
        int k = i / 128, rem = i % 128, ci = rem / 2, co = rem % 2;
        sW[(k * 2 + co) * 64 + ci] = W[i];
    }
    __syncthreads();
    int warp = (blockIdx.x * blockDim.x + threadIdx.x) >> 5;
    int lane = threadIdx.x & 31;
    if (warp >= n) return;
    size_t base = (size_t)warp * 64;
    float a0 = h[base + lane];
    float a1 = h[base + lane + 32];
    float r[6];
#pragma unroll
    for (int m = 0; m < 6; m++) {
        const float* w = sW + m * 64;
        float acc = fmaf(a1, w[lane + 32], a0 * w[lane]);
#pragma unroll
        for (int off = 16; off > 0; off >>= 1)
            acc += __shfl_down_sync(0xffffffffu, acc, off);
        r[m] = acc;
    }
    if (lane == 0) {
        float di = dis[warp];
        part[(size_t)warp * 2 + 0] = r[0] - r[4];
        part[(size_t)warp * 2 + 1] = r[1] - r[5];
        float4 z; z.x = di * r[2]; z.y = di * r[3]; z.z = di * r[4]; z.w = di * r[5];
        *reinterpret_cast<float4*>(zpack + (size_t)warp * 4) = z;
    }
}

// ---------------------------------------------------------------------------
// Combine 1->16: emits fp32 out and dis-scaled bf16 shadow
// ---------------------------------------------------------------------------
__global__ void combine_1_16(const float* __restrict__ f0, const float* __restrict__ t1,
                             const float* __restrict__ t2, const float* __restrict__ dis,
                             const float* __restrict__ W,
                             float* __restrict__ out, __nv_bfloat16* __restrict__ outb,
                             int n) {
    __shared__ float sW[48];
    if (threadIdx.x < 48) sW[threadIdx.x] = W[threadIdx.x];
    __syncthreads();
    int tid = blockIdx.x * blockDim.x + threadIdx.x;
    int node = tid >> 4;
    int co = tid & 15;
    if (node >= n) return;
    float a = f0[node];
    float b = t1[node];
    float d = 2.f * t2[node] - a;
    float acc = a * sW[co] + b * sW[16 + co] + d * sW[32 + co];
    float r = fmaxf(acc, 0.f);
    out[(size_t)node * 16 + co] = r;
    outb[(size_t)node * 16 + co] = __float2bfloat16_rn(dis[node] * r);
}

// ---------------------------------------------------------------------------
// Combine 16->32: warp per node; emits dis-scaled bf16 shadow
// ---------------------------------------------------------------------------
__global__ void combine_16_32(const float* __restrict__ f0, const float* __restrict__ t1,
                              const float* __restrict__ t2, const float* __restrict__ dis,
                              const float* __restrict__ W,
                              float* __restrict__ out, __nv_bfloat16* __restrict__ outb,
                              int n) {
    __shared__ float sW[3 * 16 * 32];
    for (int i = threadIdx.x; i < 3 * 16 * 32; i += blockDim.x) sW[i] = W[i];
    __syncthreads();
    int warp = (blockIdx.x * blockDim.x + threadIdx.x) >> 5;
    int lane = threadIdx.x & 31;
    if (warp >= n) return;
    int c = lane & 15;
    float a = f0[(size_t)warp * 16 + c];
    float b = t1[(size_t)warp * 16 + c];
    float d = 2.f * t2[(size_t)warp * 16 + c] - a;
    float acc = 0.f;
#pragma unroll
    for (int cc = 0; cc < 16; cc++) {
        float av = __shfl_sync(0xffffffffu, a, cc);
        float bv = __shfl_sync(0xffffffffu, b, cc);
        float dv = __shfl_sync(0xffffffffu, d, cc);
        acc = fmaf(av, sW[cc * 32 + lane], acc);
        acc = fmaf(bv, sW[512 + cc * 32 + lane], acc);
        acc = fmaf(dv, sW[1024 + cc * 32 + lane], acc);
    }
    float r = fmaxf(acc, 0.f);
    out[(size_t)warp * 32 + lane] = r;
    outb[(size_t)warp * 32 + lane] = __float2bfloat16_rn(dis[warp] * r);
}

// ---------------------------------------------------------------------------
// Combine 32->64: warp per node; lane computes couts {2L, 2L+1} via LDS.64
// ---------------------------------------------------------------------------
__global__ void combine_32_64(const float* __restrict__ f0, const float* __restrict__ t1,
                              const float* __restrict__ t2, const float* __restrict__ W,
                              float* __restrict__ out, int n) {
    __shared__ float sW[3 * 32 * 64];
    for (int i = threadIdx.x; i < 3 * 32 * 64; i += blockDim.x) sW[i] = W[i];
    __syncthreads();
    int warp = (blockIdx.x * blockDim.x + threadIdx.x) >> 5;
    int lane = threadIdx.x & 31;
    if (warp >= n) return;
    float a = f0[(size_t)warp * 32 + lane];
    float b = t1[(size_t)warp * 32 + lane];
    float d = 2.f * t2[(size_t)warp * 32 + lane] - a;
    float acc0 = 0.f, acc1 = 0.f;
#pragma unroll
    for (int cc = 0; cc < 32; cc++) {
        float av = __shfl_sync(0xffffffffu, a, cc);
        float bv = __shfl_sync(0xffffffffu, b, cc);
        float dv = __shfl_sync(0xffffffffu, d, cc);
        float2 w0 = *reinterpret_cast<const float2*>(sW + cc * 64 + lane * 2);
        float2 w1 = *reinterpret_cast<const float2*>(sW + 2048 + cc * 64 + lane * 2);
        float2 w2 = *reinterpret_cast<const float2*>(sW + 4096 + cc * 64 + lane * 2);
        acc0 = fmaf(av, w0.x, acc0);
        acc1 = fmaf(av, w0.y, acc1);
        acc0 = fmaf(bv, w1.x, acc0);
        acc1 = fmaf(bv, w1.y, acc1);
        acc0 = fmaf(dv, w2.x, acc0);
        acc1 = fmaf(dv, w2.y, acc1);
    }
    float2 r; r.x = fmaxf(acc0, 0.f); r.y = fmaxf(acc1, 0.f);
    *reinterpret_cast<float2*>(out + (size_t)warp * 64 + lane * 2) = r;
}

extern "C" void kernel_launch(void* const* d_in, const int* in_sizes, int n_in,
                              void* d_out, int out_size) {
    const float* x = (const float*)d_in[0];
    const int* edge_index = (const int*)d_in[1];
    const float* ea = (const float*)d_in[2];
    const float* W1 = (const float*)d_in[3];
    const float* W2 = (const float*)d_in[4];
    const float* W3 = (const float*)d_in[5];
    const float* W4 = (const float*)d_in[6];

    const int N = in_sizes[0];
    const int E = in_sizes[2];
    const int* src = edge_index;
    const int* dst = edge_index + E;

    float *deg, *dis, *xs, *bufA, *bufB, *t1, *t1s, *t2;
    int *cnt, *rs, *cur;
    unsigned long long* sstate;
    unsigned* edges;
    __nv_bfloat16 *xb, *tb;
    cudaGetSymbolAddress((void**)&deg, g_deg);
    cudaGetSymbolAddress((void**)&dis, g_dis);
    cudaGetSymbolAddress((void**)&xs, g_xs);
    cudaGetSymbolAddress((void**)&cnt, g_cnt);
    cudaGetSymbolAddress((void**)&rs, g_rs);
    cudaGetSymbolAddress((void**)&cur, g_cur);
    cudaGetSymbolAddress((void**)&sstate, g_sstate);
    cudaGetSymbolAddress((void**)&edges, g_edges);
    cudaGetSymbolAddress((void**)&bufA, g_bufA);
    cudaGetSymbolAddress((void**)&bufB, g_bufB);
    cudaGetSymbolAddress((void**)&t1, g_t1);
    cudaGetSymbolAddress((void**)&t1s, g_t1s);
    cudaGetSymbolAddress((void**)&t2, g_t2);
    cudaGetSymbolAddress((void**)&xb, g_xb);
    cudaGetSymbolAddress((void**)&tb, g_tb);

    // ---- build CSR + dis ----
    zero_build_k<<<cdiv(N, 256), 256>>>(deg, cnt, sstate, N);
    deg_hist_k<<<cdiv(cdiv(E, 4), 256), 256>>>(src, dst, ea, deg, cnt, E);
    int nb = cdiv(N, SCAN_ELEMS);
    scan_lookback_k<<<nb, SCAN_TPB>>>(cnt, sstate, rs, cur, N);
    scatter_k<<<cdiv(cdiv(E, 4), 256), 256>>>(src, dst, ea, cur, edges, E);
    dis_k<<<cdiv(N, 256), 256>>>(deg, x, dis, xs, N);

    const int WPB = 256;
    int grid_n = cdiv((long long)N * 32, WPB);

    // ---- layer 1: 1 -> 16, relu ----
    prop_c1<true><<<grid_n, WPB>>>(xs, dis, edges, rs, t1, t1s, N);
    prop_c1<false><<<grid_n, WPB>>>(t1s, dis, edges, rs, t2, nullptr, N);
    combine_1_16<<<cdiv((long long)N * 16, 256), 256>>>(x, t1, t2, dis, W1, bufA, xb, N);

    // ---- layer 2: 16 -> 32, relu (bf16 gathers) ----
    prop_c16_bf16<true><<<grid_n, WPB>>>(xb, dis, edges, rs, t1, tb, N);
    prop_c16_bf16<false><<<grid_n, WPB>>>(tb, dis, edges, rs, t2, nullptr, N);
    combine_16_32<<<grid_n, WPB>>>(bufA, t1, t2, dis, W2, bufB, xb, N);

    // ---- layer 3: 32 -> 64, relu (bf16 gathers) ----
    prop_c32_bf16<true><<<grid_n, WPB>>>(xb, dis, edges, rs, t1, tb, N);
    prop_c32_bf16<false><<<grid_n, WPB>>>(tb, dis, edges, rs, t2, nullptr, N);
    combine_32_64<<<grid_n, WPB>>>(bufB, t1, t2, W3, bufA, N);

    // ---- layer 4: 64 -> 2 via project-then-propagate ----
    gemm_head_64_2<<<grid_n, WPB>>>(bufA, dis, W4, bufB, t1, N);
    prop_csr_c4<<<grid_n, WPB>>>(t1, dis, edges, rs, t2, N);
    prop2_final_k<<<grid_n, WPB>>>(t2, bufB, dis, edges, rs, (float*)d_out, N);
}

// round 11
// speedup vs baseline: 1.0722x; 1.0722x over previous
#include <cuda_runtime.h>
#include <cuda_bf16.h>
#include <cstdint>

#define NMAX 100000
#define EMAX 3200000

// Scratch (device globals: allocation is forbidden).
__device__ float g_deg[NMAX];
__device__ float g_dis[NMAX];
__device__ float g_xs[NMAX];
__device__ int   g_cnt[NMAX];
__device__ int   g_rs[NMAX + 1];
__device__ int   g_cur[NMAX];
__device__ unsigned long long g_sstate[128];
__device__ uint2 g_edges[EMAX];         // {src, ea} sorted by dst
__device__ float g_bufA[NMAX * 64];     // layer-1 out (N*16) -> later part (N*2)
__device__ float g_bufB[NMAX * 64];     // layer-2 out (N*32) -> later zprop (N*4)
__device__ float g_t1[NMAX * 64];
__device__ float g_t1s[NMAX];
__device__ float g_t2[NMAX * 64];       // zpack (N*4)
__device__ __nv_bfloat16 g_xb[NMAX * 32];   // bf16 shadow (dis-scaled)
__device__ __nv_bfloat16 g_tb[NMAX * 32];   // bf16 shadow of t1 (dis-scaled)

static inline int cdiv(long long a, int b) { return (int)((a + b - 1) / b); }

// ===========================================================================
// Build phase (round-8 best)
// ===========================================================================
__global__ void zero_build_k(float* deg, int* cnt, unsigned long long* sstate, int n) {
    int i = blockIdx.x * blockDim.x + threadIdx.x;
    if (i < n) { deg[i] = 0.f; cnt[i] = 0; }
    if (i < 128) sstate[i] = 0ULL;
}

__global__ void deg_hist_k(const int* __restrict__ src, const int* __restrict__ dst,
                           const float* __restrict__ ea,
                           float* __restrict__ deg, int* __restrict__ cnt, int E) {
    int base = (blockIdx.x * blockDim.x + threadIdx.x) * 4;
    if (base + 3 < E) {
        int4 s = *reinterpret_cast<const int4*>(src + base);
        int4 d = *reinterpret_cast<const int4*>(dst + base);
        float4 w = *reinterpret_cast<const float4*>(ea + base);
        atomicAdd(&deg[s.x], w.x);
        atomicAdd(&deg[s.y], w.y);
        atomicAdd(&deg[s.z], w.z);
        atomicAdd(&deg[s.w], w.w);
        atomicAdd(&cnt[d.x], 1);
        atomicAdd(&cnt[d.y], 1);
        atomicAdd(&cnt[d.z], 1);
        atomicAdd(&cnt[d.w], 1);
    } else {
        for (int e = base; e < E; e++) {
            atomicAdd(&deg[src[e]], ea[e]);
            atomicAdd(&cnt[dst[e]], 1);
        }
    }
}

__global__ void dis_k(const float* __restrict__ deg, const float* __restrict__ x,
                      float* __restrict__ dis, float* __restrict__ xs, int n) {
    int i = blockIdx.x * blockDim.x + threadIdx.x;
    if (i >= n) return;
    float d = deg[i];
    float r = d > 0.f ? rsqrtf(d) : 0.f;
    dis[i] = r;
    xs[i] = r * x[i];
}

#define SCAN_TPB 256
#define SCAN_ELEMS 1024

__global__ void scan_lookback_k(const int* __restrict__ cnt,
                                unsigned long long* __restrict__ sstate,
                                int* __restrict__ rs, int* __restrict__ cur, int n) {
    int b = blockIdx.x;
    int base = b * SCAN_ELEMS + threadIdx.x * 4;
    int c0 = 0, c1 = 0, c2 = 0, c3 = 0;
    if (base + 3 < n) {
        int4 v = *reinterpret_cast<const int4*>(cnt + base);
        c0 = v.x; c1 = v.y; c2 = v.z; c3 = v.w;
    } else {
        if (base + 0 < n) c0 = cnt[base + 0];
        if (base + 1 < n) c1 = cnt[base + 1];
        if (base + 2 < n) c2 = cnt[base + 2];
        if (base + 3 < n) c3 = cnt[base + 3];
    }
    int ts = c0 + c1 + c2 + c3;
    int lane = threadIdx.x & 31, wid = threadIdx.x >> 5;
    int inc = ts;
#pragma unroll
    for (int o = 1; o < 32; o <<= 1) {
        int v = __shfl_up_sync(0xffffffffu, inc, o);
        if (lane >= o) inc += v;
    }
    __shared__ int wsum[SCAN_TPB / 32];
    __shared__ int woff[SCAN_TPB / 32];
    __shared__ int s_base;
    __shared__ int s_total;
    if (lane == 31) wsum[wid] = inc;
    __syncthreads();
    if (threadIdx.x == 0) {
        int r = 0;
#pragma unroll
        for (int w = 0; w < SCAN_TPB / 32; w++) { woff[w] = r; r += wsum[w]; }
        s_total = r;
        atomicExch(&sstate[b], (1ULL << 62) | (unsigned)r);
        int excl = 0;
        for (int p = b - 1; p >= 0; ) {
            unsigned long long s;
            do { s = atomicAdd(&sstate[p], 0ULL); } while ((s >> 62) == 0);
            excl += (int)(unsigned)s;
            if ((s >> 62) == 2ULL) break;
            p--;
        }
        atomicExch(&sstate[b], (2ULL << 62) | (unsigned)(excl + r));
        s_base = excl;
    }
    __syncthreads();
    int r = s_base + (inc - ts) + woff[wid];
    if (base + 0 < n) { rs[base + 0] = r; cur[base + 0] = r; r += c0; }
    if (base + 1 < n) { rs[base + 1] = r; cur[base + 1] = r; r += c1; }
    if (base + 2 < n) { rs[base + 2] = r; cur[base + 2] = r; r += c2; }
    if (base + 3 < n) { rs[base + 3] = r; cur[base + 3] = r; r += c3; }
    if (b == gridDim.x - 1 && threadIdx.x == 0) rs[n] = s_base + s_total;
}

__global__ void scatter_k(const int* __restrict__ src, const int* __restrict__ dst,
                          const float* __restrict__ ea,
                          int* __restrict__ cur, uint2* __restrict__ ed, int E) {
    int base = (blockIdx.x * blockDim.x + threadIdx.x) * 4;
    if (base + 3 < E) {
        int4 s = *reinterpret_cast<const int4*>(src + base);
        int4 d = *reinterpret_cast<const int4*>(dst + base);
        float4 w = *reinterpret_cast<const float4*>(ea + base);
        int p0 = atomicAdd(&cur[d.x], 1);
        int p1 = atomicAdd(&cur[d.y], 1);
        int p2 = atomicAdd(&cur[d.z], 1);
        int p3 = atomicAdd(&cur[d.w], 1);
        ed[p0] = make_uint2((unsigned)s.x, __float_as_uint(w.x));
        ed[p1] = make_uint2((unsigned)s.y, __float_as_uint(w.y));
        ed[p2] = make_uint2((unsigned)s.z, __float_as_uint(w.z));
        ed[p3] = make_uint2((unsigned)s.w, __float_as_uint(w.w));
    } else {
        for (int e = base; e < E; e++) {
            int slot = atomicAdd(&cur[dst[e]], 1);
            ed[slot] = make_uint2((unsigned)src[e], __float_as_uint(ea[e]));
        }
    }
}

// ===========================================================================
// Layer 1, pass 1: t1 = P(xs);  t1s = dis*t1
// ===========================================================================
__global__ void prop_c1_p1(const float* __restrict__ xs, const float* __restrict__ dis,
                           const uint2* __restrict__ ed, const int* __restrict__ rs,
                           float* __restrict__ out, float* __restrict__ outs, int N) {
    int warp = (blockIdx.x * blockDim.x + threadIdx.x) >> 5;
    int lane = threadIdx.x & 31;
    if (warp >= N) return;
    int beg = rs[warp], end = rs[warp + 1];
    float acc = 0.f;
    for (int j = beg + lane; j < end; j += 32) {
        uint2 e = ed[j];
        acc += __uint_as_float(e.y) * __ldg(xs + e.x);
    }
#pragma unroll
    for (int off = 16; off > 0; off >>= 1)
        acc += __shfl_down_sync(0xffffffffu, acc, off);
    if (lane == 0) {
        float di = dis[warp];
        float r = -di * acc;
        out[warp] = r;
        outs[warp] = di * r;
    }
}

// ===========================================================================
// Layer 1 fused pass 2 + combine 1->16:
//   t2 = P(t1s) in-register, out = relu(a*W0 + b*W1 + (2*t2-a)*W2)
// ===========================================================================
__global__ void fused_l1(const float* __restrict__ t1s, const float* __restrict__ x,
                         const float* __restrict__ t1, const float* __restrict__ dis,
                         const float* __restrict__ W,
                         float* __restrict__ out, __nv_bfloat16* __restrict__ outb,
                         const uint2* __restrict__ ed, const int* __restrict__ rs, int N) {
    __shared__ float sW[48];
    if (threadIdx.x < 48) sW[threadIdx.x] = W[threadIdx.x];
    __syncthreads();
    int warp = (blockIdx.x * blockDim.x + threadIdx.x) >> 5;
    int lane = threadIdx.x & 31;
    if (warp >= N) return;
    int beg = rs[warp], end = rs[warp + 1];
    float acc = 0.f;
    for (int j = beg + lane; j < end; j += 32) {
        uint2 e = ed[j];
        acc += __uint_as_float(e.y) * __ldg(t1s + e.x);
    }
#pragma unroll
    for (int off = 16; off > 0; off >>= 1)
        acc += __shfl_xor_sync(0xffffffffu, acc, off);  // replicated on all lanes
    float di = dis[warp];
    float t2v = -di * acc;
    float a = x[warp];
    float b = t1[warp];
    if (lane < 16) {
        float d = 2.f * t2v - a;
        float r = fmaxf(a * sW[lane] + b * sW[16 + lane] + d * sW[32 + lane], 0.f);
        out[(size_t)warp * 16 + lane] = r;
        outb[(size_t)warp * 16 + lane] = __float2bfloat16_rn(di * r);
    }
}

// ===========================================================================
// Layer 2/3 pass-1 props (round-8 form, WRITE_B always true here)
// ===========================================================================
__global__ void prop_c16_p1(const __nv_bfloat16* __restrict__ xb,
                            const float* __restrict__ dis,
                            const uint2* __restrict__ ed, const int* __restrict__ rs,
                            float* __restrict__ out, __nv_bfloat16* __restrict__ outb,
                            int N) {
    int warp = (blockIdx.x * blockDim.x + threadIdx.x) >> 5;
    int lane = threadIdx.x & 31;
    if (warp >= N) return;
    int grp = lane >> 3;
    int sub = lane & 7;
    int beg = rs[warp], end = rs[warp + 1];
    float ax = 0.f, ay = 0.f;
    int j = beg;
    for (; j + 16 <= end; j += 16) {
        uint2 e[4];
#pragma unroll
        for (int k = 0; k < 4; k++) e[k] = ed[j + k * 4 + grp];
        float2 f[4];
#pragma unroll
        for (int k = 0; k < 4; k++) {
            __nv_bfloat162 v = *reinterpret_cast<const __nv_bfloat162*>(
                xb + (size_t)e[k].x * 16 + sub * 2);
            f[k] = __bfloat1622float2(v);
        }
#pragma unroll
        for (int k = 0; k < 4; k++) {
            float w = __uint_as_float(e[k].y);
            ax = fmaf(w, f[k].x, ax);
            ay = fmaf(w, f[k].y, ay);
        }
    }
    for (; j < end; j += 4) {
        int idx = j + grp;
        if (idx < end) {
            uint2 e = ed[idx];
            __nv_bfloat162 v = *reinterpret_cast<const __nv_bfloat162*>(
                xb + (size_t)e.x * 16 + sub * 2);
            float2 f = __bfloat1622float2(v);
            float w = __uint_as_float(e.y);
            ax = fmaf(w, f.x, ax); ay = fmaf(w, f.y, ay);
        }
    }
    ax += __shfl_xor_sync(0xffffffffu, ax, 8);
    ay += __shfl_xor_sync(0xffffffffu, ay, 8);
    ax += __shfl_xor_sync(0xffffffffu, ax, 16);
    ay += __shfl_xor_sync(0xffffffffu, ay, 16);
    if (lane < 8) {
        float di = dis[warp];
        float2 r; r.x = -di * ax; r.y = -di * ay;
        *reinterpret_cast<float2*>(out + (size_t)warp * 16 + sub * 2) = r;
        float2 s; s.x = di * r.x; s.y = di * r.y;
        __nv_bfloat162 b = __float22bfloat162_rn(s);
        *reinterpret_cast<__nv_bfloat162*>(outb + (size_t)warp * 16 + sub * 2) = b;
    }
}

__global__ void prop_c32_p1(const __nv_bfloat16* __restrict__ xb,
                            const float* __restrict__ dis,
                            const uint2* __restrict__ ed, const int* __restrict__ rs,
                            float* __restrict__ out, __nv_bfloat16* __restrict__ outb,
                            int N) {
    int warp = (blockIdx.x * blockDim.x + threadIdx.x) >> 5;
    int lane = threadIdx.x & 31;
    if (warp >= N) return;
    int grp = lane >> 4;
    int sub = lane & 15;
    int beg = rs[warp], end = rs[warp + 1];
    float ax = 0.f, ay = 0.f;
    int j = beg;
    for (; j + 16 <= end; j += 16) {
        uint2 e[8];
#pragma unroll
        for (int k = 0; k < 8; k++) e[k] = ed[j + k * 2 + grp];
        float2 f[8];
#pragma unroll
        for (int k = 0; k < 8; k++) {
            __nv_bfloat162 v = *reinterpret_cast<const __nv_bfloat162*>(
                xb + (size_t)e[k].x * 32 + sub * 2);
            f[k] = __bfloat1622float2(v);
        }
#pragma unroll
        for (int k = 0; k < 8; k++) {
            float w = __uint_as_float(e[k].y);
            ax = fmaf(w, f[k].x, ax);
            ay = fmaf(w, f[k].y, ay);
        }
    }
    for (; j < end; j += 2) {
        int idx = j + grp;
        if (idx < end) {
            uint2 e = ed[idx];
            __nv_bfloat162 v = *reinterpret_cast<const __nv_bfloat162*>(
                xb + (size_t)e.x * 32 + sub * 2);
            float2 f = __bfloat1622float2(v);
            float w = __uint_as_float(e.y);
            ax = fmaf(w, f.x, ax); ay = fmaf(w, f.y, ay);
        }
    }
    ax += __shfl_xor_sync(0xffffffffu, ax, 16);
    ay += __shfl_xor_sync(0xffffffffu, ay, 16);
    if (lane < 16) {
        float di = dis[warp];
        float2 r; r.x = -di * ax; r.y = -di * ay;
        *reinterpret_cast<float2*>(out + (size_t)warp * 32 + sub * 2) = r;
        float2 s; s.x = di * r.x; s.y = di * r.y;
        __nv_bfloat162 b = __float22bfloat162_rn(s);
        *reinterpret_cast<__nv_bfloat162*>(outb + (size_t)warp * 32 + sub * 2) = b;
    }
}

// ===========================================================================
// Layer 2 fused pass 2 + combine 16->32.
// Tx2 stays in registers: after xor-reduce, every lane holds channels
// {2*(lane&7), 2*(lane&7)+1} of P(t1) (pre -dis scale).
// ===========================================================================
__global__ void fused_l2(const __nv_bfloat16* __restrict__ tb,
                         const float* __restrict__ f0, const float* __restrict__ t1,
                         const float* __restrict__ dis, const float* __restrict__ W,
                         float* __restrict__ out, __nv_bfloat16* __restrict__ outb,
                         const uint2* __restrict__ ed, const int* __restrict__ rs, int N) {
    __shared__ float sW[3 * 16 * 32];
    for (int i = threadIdx.x; i < 3 * 16 * 32; i += blockDim.x) sW[i] = W[i];
    __syncthreads();
    int warp = (blockIdx.x * blockDim.x + threadIdx.x) >> 5;
    int lane = threadIdx.x & 31;
    if (warp >= N) return;
    int grp = lane >> 3;
    int sub = lane & 7;
    int beg = rs[warp], end = rs[warp + 1];
    float ax = 0.f, ay = 0.f;
    int j = beg;
    for (; j + 16 <= end; j += 16) {
        uint2 e[4];
#pragma unroll
        for (int k = 0; k < 4; k++) e[k] = ed[j + k * 4 + grp];
        float2 f[4];
#pragma unroll
        for (int k = 0; k < 4; k++) {
            __nv_bfloat162 v = *reinterpret_cast<const __nv_bfloat162*>(
                tb + (size_t)e[k].x * 16 + sub * 2);
            f[k] = __bfloat1622float2(v);
        }
#pragma unroll
        for (int k = 0; k < 4; k++) {
            float w = __uint_as_float(e[k].y);
            ax = fmaf(w, f[k].x, ax);
            ay = fmaf(w, f[k].y, ay);
        }
    }
    for (; j < end; j += 4) {
        int idx = j + grp;
        if (idx < end) {
            uint2 e = ed[idx];
            __nv_bfloat162 v = *reinterpret_cast<const __nv_bfloat162*>(
                tb + (size_t)e.x * 16 + sub * 2);
            float2 f = __bfloat1622float2(v);
            float w = __uint_as_float(e.y);
            ax = fmaf(w, f.x, ax); ay = fmaf(w, f.y, ay);
        }
    }
    ax += __shfl_xor_sync(0xffffffffu, ax, 8);
    ay += __shfl_xor_sync(0xffffffffu, ay, 8);
    ax += __shfl_xor_sync(0xffffffffu, ax, 16);
    ay += __shfl_xor_sync(0xffffffffu, ay, 16);

    float di = dis[warp];
    float t2x = -di * ax;   // channel 2*sub
    float t2y = -di * ay;   // channel 2*sub+1

    int c = lane & 15;
    float a = f0[(size_t)warp * 16 + c];
    float b = t1[(size_t)warp * 16 + c];
    float acc = 0.f;
#pragma unroll
    for (int cc = 0; cc < 16; cc++) {
        float av = __shfl_sync(0xffffffffu, a, cc);
        float bv = __shfl_sync(0xffffffffu, b, cc);
        float t2v = (cc & 1) ? __shfl_sync(0xffffffffu, t2y, cc >> 1)
                             : __shfl_sync(0xffffffffu, t2x, cc >> 1);
        float dv = 2.f * t2v - av;
        acc = fmaf(av, sW[cc * 32 + lane], acc);
        acc = fmaf(bv, sW[512 + cc * 32 + lane], acc);
        acc = fmaf(dv, sW[1024 + cc * 32 + lane], acc);
    }
    float r = fmaxf(acc, 0.f);
    out[(size_t)warp * 32 + lane] = r;
    outb[(size_t)warp * 32 + lane] = __float2bfloat16_rn(di * r);
}

// ===========================================================================
// Layer 3 fused pass 2 + combine 32->64 + head GEMM 64->2.
// Emits only part (N*2) and zpack (N*4); layer-3 activations never hit memory.
// ===========================================================================
__global__ void fused_l3(const __nv_bfloat16* __restrict__ tb,
                         const float* __restrict__ f0, const float* __restrict__ t1,
                         const float* __restrict__ dis,
                         const float* __restrict__ W3, const float* __restrict__ W4,
                         float* __restrict__ part, float* __restrict__ zpack,
                         const uint2* __restrict__ ed, const int* __restrict__ rs, int N) {
    __shared__ float sW[3 * 32 * 64];   // W3 as-is
    __shared__ float sW4[6 * 64];       // [(k*2+co)*64 + ci]
    for (int i = threadIdx.x; i < 3 * 32 * 64; i += blockDim.x) sW[i] = W3[i];
    for (int i = threadIdx.x; i < 384; i += blockDim.x) {
        int k = i / 128, rem = i % 128, ci = rem / 2, co = rem % 2;
        sW4[(k * 2 + co) * 64 + ci] = W4[i];
    }
    __syncthreads();
    int warp = (blockIdx.x * blockDim.x + threadIdx.x) >> 5;
    int lane = threadIdx.x & 31;
    if (warp >= N) return;
    int grp = lane >> 4;
    int sub = lane & 15;
    int beg = rs[warp], end = rs[warp + 1];
    float ax = 0.f, ay = 0.f;
    int j = beg;
    for (; j + 16 <= end; j += 16) {
        uint2 e[8];
#pragma unroll
        for (int k = 0; k < 8; k++) e[k] = ed[j + k * 2 + grp];
        float2 f[8];
#pragma unroll
        for (int k = 0; k < 8; k++) {
            __nv_bfloat162 v = *reinterpret_cast<const __nv_bfloat162*>(
                tb + (size_t)e[k].x * 32 + sub * 2);
            f[k] = __bfloat1622float2(v);
        }
#pragma unroll
        for (int k = 0; k < 8; k++) {
            float w = __uint_as_float(e[k].y);
            ax = fmaf(w, f[k].x, ax);
            ay = fmaf(w, f[k].y, ay);
        }
    }
    for (; j < end; j += 2) {
        int idx = j + grp;
        if (idx < end) {
            uint2 e = ed[idx];
            __nv_bfloat162 v = *reinterpret_cast<const __nv_bfloat162*>(
                tb + (size_t)e.x * 32 + sub * 2);
            float2 f = __bfloat1622float2(v);
            float w = __uint_as_float(e.y);
            ax = fmaf(w, f.x, ax); ay = fmaf(w, f.y, ay);
        }
    }
    ax += __shfl_xor_sync(0xffffffffu, ax, 16);
    ay += __shfl_xor_sync(0xffffffffu, ay, 16);

    float di = dis[warp];
    float t2x = -di * ax;   // channel 2*sub
    float t2y = -di * ay;   // channel 2*sub+1

    // combine 32->64: lane computes couts {2*lane, 2*lane+1}
    float a = f0[(size_t)warp * 32 + lane];
    float b = t1[(size_t)warp * 32 + lane];
    float acc0 = 0.f, acc1 = 0.f;
#pragma unroll
    for (int cc = 0; cc < 32; cc++) {
        float av = __shfl_sync(0xffffffffu, a, cc);
        float bv = __shfl_sync(0xffffffffu, b, cc);
        float t2v = (cc & 1) ? __shfl_sync(0xffffffffu, t2y, cc >> 1)
                             : __shfl_sync(0xffffffffu, t2x, cc >> 1);
        float dv = 2.f * t2v - av;
        float2 w0 = *reinterpret_cast<const float2*>(sW + cc * 64 + lane * 2);
        float2 w1 = *reinterpret_cast<const float2*>(sW + 2048 + cc * 64 + lane * 2);
        float2 w2 = *reinterpret_cast<const float2*>(sW + 4096 + cc * 64 + lane * 2);
        acc0 = fmaf(av, w0.x, acc0);
        acc1 = fmaf(av, w0.y, acc1);
        acc0 = fmaf(bv, w1.x, acc0);
        acc1 = fmaf(bv, w1.y, acc1);
        acc0 = fmaf(dv, w2.x, acc0);
        acc1 = fmaf(dv, w2.y, acc1);
    }
    float h0 = fmaxf(acc0, 0.f);   // h[2*lane]
    float h1 = fmaxf(acc1, 0.f);   // h[2*lane+1]

    // head GEMM: r[m] = sum_ci h[ci] * sW4[m*64 + ci]
    float r[6];
#pragma unroll
    for (int m = 0; m < 6; m++) {
        const float* w = sW4 + m * 64;
        float racc = fmaf(h1, w[2 * lane + 1], h0 * w[2 * lane]);
#pragma unroll
        for (int off = 16; off > 0; off >>= 1)
            racc += __shfl_down_sync(0xffffffffu, racc, off);
        r[m] = racc;
    }
    if (lane == 0) {
        part[(size_t)warp * 2 + 0] = r[0] - r[4];
        part[(size_t)warp * 2 + 1] = r[1] - r[5];
        float4 z; z.x = di * r[2]; z.y = di * r[3]; z.z = di * r[4]; z.w = di * r[5];
        *reinterpret_cast<float4*>(zpack + (size_t)warp * 4) = z;
    }
}

// ===========================================================================
// Layer-4 tail props (round-8 form)
// ===========================================================================
__global__ void prop_csr_c4(const float* __restrict__ zs, const float* __restrict__ dis,
                            const uint2* __restrict__ ed, const int* __restrict__ rs,
                            float* __restrict__ out, int N) {
    int warp = (blockIdx.x * blockDim.x + threadIdx.x) >> 5;
    int lane = threadIdx.x & 31;
    if (warp >= N) return;
    int k = lane >> 2;
    int c = lane & 3;
    int beg = rs[warp], end = rs[warp + 1];
    float acc = 0.f;
    for (int j = beg + k; j < end; j += 8) {
        uint2 e = ed[j];
        acc = fmaf(__uint_as_float(e.y), __ldg(zs + (size_t)e.x * 4 + c), acc);
    }
#pragma unroll
    for (int off = 16; off >= 4; off >>= 1)
        acc += __shfl_down_sync(0xffffffffu, acc, off);
    if (lane < 4) {
        float di = dis[warp];
        float r = -di * acc;
        out[(size_t)warp * 4 + c] = (c < 2) ? r : di * r;
    }
}

__global__ void prop2_final_k(const float* __restrict__ t4, const float* __restrict__ part,
                              const float* __restrict__ dis,
                              const uint2* __restrict__ ed, const int* __restrict__ rs,
                              float* __restrict__ y, int N) {
    int warp = (blockIdx.x * blockDim.x + threadIdx.x) >> 5;
    int lane = threadIdx.x & 31;
    if (warp >= N) return;
    int k = lane >> 1;
    int c = lane & 1;
    int beg = rs[warp], end = rs[warp + 1];
    float acc = 0.f;
    for (int j = beg + k; j < end; j += 16) {
        uint2 e = ed[j];
        acc = fmaf(__uint_as_float(e.y), __ldg(t4 + (size_t)e.x * 4 + 2 + c), acc);
    }
#pragma unroll
    for (int off = 16; off >= 2; off >>= 1)
        acc += __shfl_down_sync(0xffffffffu, acc, off);
    if (lane < 2) {
        float w = -dis[warp] * acc;
        y[(size_t)warp * 2 + c] = part[(size_t)warp * 2 + c]
                                + t4[(size_t)warp * 4 + c] + 2.f * w;
    }
}

extern "C" void kernel_launch(void* const* d_in, const int* in_sizes, int n_in,
                              void* d_out, int out_size) {
    const float* x = (const float*)d_in[0];
    const int* edge_index = (const int*)d_in[1];
    const float* ea = (const float*)d_in[2];
    const float* W1 = (const float*)d_in[3];
    const float* W2 = (const float*)d_in[4];
    const float* W3 = (const float*)d_in[5];
    const float* W4 = (const float*)d_in[6];

    const int N = in_sizes[0];
    const int E = in_sizes[2];
    const int* src = edge_index;
    const int* dst = edge_index + E;

    float *deg, *dis, *xs, *bufA, *bufB, *t1, *t1s, *t2;
    int *cnt, *rs, *cur;
    unsigned long long* sstate;
    uint2* edges;
    __nv_bfloat16 *xb, *tb;
    cudaGetSymbolAddress((void**)&deg, g_deg);
    cudaGetSymbolAddress((void**)&dis, g_dis);
    cudaGetSymbolAddress((void**)&xs, g_xs);
    cudaGetSymbolAddress((void**)&cnt, g_cnt);
    cudaGetSymbolAddress((void**)&rs, g_rs);
    cudaGetSymbolAddress((void**)&cur, g_cur);
    cudaGetSymbolAddress((void**)&sstate, g_sstate);
    cudaGetSymbolAddress((void**)&edges, g_edges);
    cudaGetSymbolAddress((void**)&bufA, g_bufA);
    cudaGetSymbolAddress((void**)&bufB, g_bufB);
    cudaGetSymbolAddress((void**)&t1, g_t1);
    cudaGetSymbolAddress((void**)&t1s, g_t1s);
    cudaGetSymbolAddress((void**)&t2, g_t2);
    cudaGetSymbolAddress((void**)&xb, g_xb);
    cudaGetSymbolAddress((void**)&tb, g_tb);

    // ---- build CSR + dis ----
    zero_build_k<<<cdiv(N, 256), 256>>>(deg, cnt, sstate, N);
    deg_hist_k<<<cdiv(cdiv(E, 4), 256), 256>>>(src, dst, ea, deg, cnt, E);
    int nb = cdiv(N, SCAN_ELEMS);
    scan_lookback_k<<<nb, SCAN_TPB>>>(cnt, sstate, rs, cur, N);
    scatter_k<<<cdiv(cdiv(E, 4), 256), 256>>>(src, dst, ea, cur, edges, E);
    dis_k<<<cdiv(N, 256), 256>>>(deg, x, dis, xs, N);

    const int WPB = 256;
    int grid_n = cdiv((long long)N * 32, WPB);

    // ---- layer 1: 1 -> 16, relu (pass2 + combine fused) ----
    prop_c1_p1<<<grid_n, WPB>>>(xs, dis, edges, rs, t1, t1s, N);
    fused_l1<<<grid_n, WPB>>>(t1s, x, t1, dis, W1, bufA, xb, edges, rs, N);

    // ---- layer 2: 16 -> 32, relu (pass2 + combine fused) ----
    prop_c16_p1<<<grid_n, WPB>>>(xb, dis, edges, rs, t1, tb, N);
    fused_l2<<<grid_n, WPB>>>(tb, bufA, t1, dis, W2, bufB, xb, edges, rs, N);

    // ---- layer 3: 32 -> 64 + head GEMM (pass2 + combine + head fused) ----
    prop_c32_p1<<<grid_n, WPB>>>(xb, dis, edges, rs, t1, tb, N);
    fused_l3<<<grid_n, WPB>>>(tb, bufB, t1, dis, W3, W4, bufA, t2, edges, rs, N);

    // ---- layer 4 tail: prop zpack, then final combine ----
    prop_csr_c4<<<grid_n, WPB>>>(t2, dis, edges, rs, bufB, N);
    prop2_final_k<<<grid_n, WPB>>>(bufB, bufA, dis, edges, rs, (float*)d_out, N);
}

// round 13
// speedup vs baseline: 1.2538x; 1.1694x over previous
#include <cuda_runtime.h>
#include <cuda_bf16.h>
#include <cstdint>

#define NMAX 100000
#define EMAX 3200000

// Scratch (device globals: allocation is forbidden).
__device__ float g_deg[NMAX];
__device__ float g_dis[NMAX];
__device__ float g_xs[NMAX];
__device__ int   g_cnt[NMAX];
__device__ int   g_rs[NMAX + 1];
__device__ int   g_cur[NMAX];
__device__ unsigned long long g_sstate[128];
__device__ uint2 g_edges[EMAX];         // {src, ea} sorted by dst
__device__ float g_bufA[NMAX * 64];     // layer-1 out (N*16) -> later part (N*2)
__device__ float g_bufB[NMAX * 64];     // layer-2 out (N*32) -> later zprop (N*4)
__device__ float g_t1[NMAX * 64];
__device__ float g_t1s[NMAX];
__device__ float g_t2[NMAX * 64];       // zpack (N*4)
__device__ __nv_bfloat16 g_xb[NMAX * 32];   // bf16 shadow (dis-scaled)
__device__ __nv_bfloat16 g_tb[NMAX * 32];   // bf16 shadow of t1 (dis-scaled)
__device__ unsigned g_wbt[64 * 96];         // W3 as Bt[co][k], tf32 bits

static inline int cdiv(long long a, int b) { return (int)((a + b - 1) / b); }

__device__ __forceinline__ unsigned to_tf32(float v) {
    unsigned u;
    asm("cvt.rna.tf32.f32 %0, %1;" : "=r"(u) : "f"(v));
    return u;
}

// ===========================================================================
// Build phase
// ===========================================================================
__global__ void zero_build_k(float* deg, int* cnt, unsigned long long* sstate, int n) {
    int i = blockIdx.x * blockDim.x + threadIdx.x;
    if (i < n) { deg[i] = 0.f; cnt[i] = 0; }
    if (i < 128) sstate[i] = 0ULL;
}

__global__ void deg_hist_k(const int* __restrict__ src, const int* __restrict__ dst,
                           const float* __restrict__ ea,
                           float* __restrict__ deg, int* __restrict__ cnt, int E) {
    int base = (blockIdx.x * blockDim.x + threadIdx.x) * 4;
    if (base + 3 < E) {
        int4 s = *reinterpret_cast<const int4*>(src + base);
        int4 d = *reinterpret_cast<const int4*>(dst + base);
        float4 w = *reinterpret_cast<const float4*>(ea + base);
        atomicAdd(&deg[s.x], w.x);
        atomicAdd(&deg[s.y], w.y);
        atomicAdd(&deg[s.z], w.z);
        atomicAdd(&deg[s.w], w.w);
        atomicAdd(&cnt[d.x], 1);
        atomicAdd(&cnt[d.y], 1);
        atomicAdd(&cnt[d.z], 1);
        atomicAdd(&cnt[d.w], 1);
    } else {
        for (int e = base; e < E; e++) {
            atomicAdd(&deg[src[e]], ea[e]);
            atomicAdd(&cnt[dst[e]], 1);
        }
    }
}

__global__ void dis_k(const float* __restrict__ deg, const float* __restrict__ x,
                      float* __restrict__ dis, float* __restrict__ xs, int n) {
    int i = blockIdx.x * blockDim.x + threadIdx.x;
    if (i >= n) return;
    float d = deg[i];
    float r = d > 0.f ? rsqrtf(d) : 0.f;
    dis[i] = r;
    xs[i] = r * x[i];
}

#define SCAN_TPB 256
#define SCAN_ELEMS 1024

__global__ void scan_lookback_k(const int* __restrict__ cnt,
                                unsigned long long* __restrict__ sstate,
                                int* __restrict__ rs, int* __restrict__ cur, int n) {
    int b = blockIdx.x;
    int base = b * SCAN_ELEMS + threadIdx.x * 4;
    int c0 = 0, c1 = 0, c2 = 0, c3 = 0;
    if (base + 3 < n) {
        int4 v = *reinterpret_cast<const int4*>(cnt + base);
        c0 = v.x; c1 = v.y; c2 = v.z; c3 = v.w;
    } else {
        if (base + 0 < n) c0 = cnt[base + 0];
        if (base + 1 < n) c1 = cnt[base + 1];
        if (base + 2 < n) c2 = cnt[base + 2];
        if (base + 3 < n) c3 = cnt[base + 3];
    }
    int ts = c0 + c1 + c2 + c3;
    int lane = threadIdx.x & 31, wid = threadIdx.x >> 5;
    int inc = ts;
#pragma unroll
    for (int o = 1; o < 32; o <<= 1) {
        int v = __shfl_up_sync(0xffffffffu, inc, o);
        if (lane >= o) inc += v;
    }
    __shared__ int wsum[SCAN_TPB / 32];
    __shared__ int woff[SCAN_TPB / 32];
    __shared__ int s_base;
    __shared__ int s_total;
    if (lane == 31) wsum[wid] = inc;
    __syncthreads();
    if (threadIdx.x == 0) {
        int r = 0;
#pragma unroll
        for (int w = 0; w < SCAN_TPB / 32; w++) { woff[w] = r; r += wsum[w]; }
        s_total = r;
        atomicExch(&sstate[b], (1ULL << 62) | (unsigned)r);
        int excl = 0;
        for (int p = b - 1; p >= 0; ) {
            unsigned long long s;
            do { s = atomicAdd(&sstate[p], 0ULL); } while ((s >> 62) == 0);
            excl += (int)(unsigned)s;
            if ((s >> 62) == 2ULL) break;
            p--;
        }
        atomicExch(&sstate[b], (2ULL << 62) | (unsigned)(excl + r));
        s_base = excl;
    }
    __syncthreads();
    int r = s_base + (inc - ts) + woff[wid];
    if (base + 0 < n) { rs[base + 0] = r; cur[base + 0] = r; r += c0; }
    if (base + 1 < n) { rs[base + 1] = r; cur[base + 1] = r; r += c1; }
    if (base + 2 < n) { rs[base + 2] = r; cur[base + 2] = r; r += c2; }
    if (base + 3 < n) { rs[base + 3] = r; cur[base + 3] = r; r += c3; }
    if (b == gridDim.x - 1 && threadIdx.x == 0) rs[n] = s_base + s_total;
}

// 1 edge/thread (measured best: 43.5us)
__global__ void scatter_k(const int* __restrict__ src, const int* __restrict__ dst,
                          const float* __restrict__ ea,
                          int* __restrict__ cur, uint2* __restrict__ ed, int E) {
    int e = blockIdx.x * blockDim.x + threadIdx.x;
    if (e >= E) return;
    int d = dst[e];
    int slot = atomicAdd(&cur[d], 1);
    ed[slot] = make_uint2((unsigned)src[e], __float_as_uint(ea[e]));
}

// W3 -> Bt[co][k] tf32 bits, k in 0..95 over [W3_0; W3_1; W3_2]
__global__ void wprep3_k(const float* __restrict__ W, unsigned* __restrict__ wbt) {
    int i = blockIdx.x * blockDim.x + threadIdx.x;
    if (i >= 64 * 96) return;
    int co = i / 96, k = i % 96;
    float v = W[(k >> 5) * 2048 + (k & 31) * 64 + co];
    wbt[i] = to_tf32(v);
}

// ===========================================================================
// Layer 1
// ===========================================================================
__global__ void prop_c1_p1(const float* __restrict__ xs, const float* __restrict__ dis,
                           const uint2* __restrict__ ed, const int* __restrict__ rs,
                           float* __restrict__ out, float* __restrict__ outs, int N) {
    int warp = (blockIdx.x * blockDim.x + threadIdx.x) >> 5;
    int lane = threadIdx.x & 31;
    if (warp >= N) return;
    int beg = rs[warp], end = rs[warp + 1];
    float acc = 0.f;
    for (int j = beg + lane; j < end; j += 32) {
        uint2 e = ed[j];
        acc += __uint_as_float(e.y) * __ldg(xs + e.x);
    }
#pragma unroll
    for (int off = 16; off > 0; off >>= 1)
        acc += __shfl_down_sync(0xffffffffu, acc, off);
    if (lane == 0) {
        float di = dis[warp];
        float r = -di * acc;
        out[warp] = r;
        outs[warp] = di * r;
    }
}

__global__ void fused_l1(const float* __restrict__ t1s, const float* __restrict__ x,
                         const float* __restrict__ t1, const float* __restrict__ dis,
                         const float* __restrict__ W,
                         float* __restrict__ out, __nv_bfloat16* __restrict__ outb,
                         const uint2* __restrict__ ed, const int* __restrict__ rs, int N) {
    __shared__ float sW[48];
    if (threadIdx.x < 48) sW[threadIdx.x] = W[threadIdx.x];
    __syncthreads();
    int warp = (blockIdx.x * blockDim.x + threadIdx.x) >> 5;
    int lane = threadIdx.x & 31;
    if (warp >= N) return;
    int beg = rs[warp], end = rs[warp + 1];
    float acc = 0.f;
    for (int j = beg + lane; j < end; j += 32) {
        uint2 e = ed[j];
        acc += __uint_as_float(e.y) * __ldg(t1s + e.x);
    }
#pragma unroll
    for (int off = 16; off > 0; off >>= 1)
        acc += __shfl_xor_sync(0xffffffffu, acc, off);
    float di = dis[warp];
    float t2v = -di * acc;
    float a = x[warp];
    float b = t1[warp];
    if (lane < 16) {
        float d = 2.f * t2v - a;
        float r = fmaxf(a * sW[lane] + b * sW[16 + lane] + d * sW[32 + lane], 0.f);
        out[(size_t)warp * 16 + lane] = r;
        outb[(size_t)warp * 16 + lane] = __float2bfloat16_rn(di * r);
    }
}

// ===========================================================================
// Layer 2/3 pass-1 props
// ===========================================================================
__global__ void prop_c16_p1(const __nv_bfloat16* __restrict__ xb,
                            const float* __restrict__ dis,
                            const uint2* __restrict__ ed, const int* __restrict__ rs,
                            float* __restrict__ out, __nv_bfloat16* __restrict__ outb,
                            int N) {
    int warp = (blockIdx.x * blockDim.x + threadIdx.x) >> 5;
    int lane = threadIdx.x & 31;
    if (warp >= N) return;
    int grp = lane >> 3;
    int sub = lane & 7;
    int beg = rs[warp], end = rs[warp + 1];
    float ax = 0.f, ay = 0.f;
    int j = beg;
    for (; j + 16 <= end; j += 16) {
        uint2 e[4];
#pragma unroll
        for (int k = 0; k < 4; k++) e[k] = ed[j + k * 4 + grp];
        float2 f[4];
#pragma unroll
        for (int k = 0; k < 4; k++) {
            __nv_bfloat162 v = *reinterpret_cast<const __nv_bfloat162*>(
                xb + (size_t)e[k].x * 16 + sub * 2);
            f[k] = __bfloat1622float2(v);
        }
#pragma unroll
        for (int k = 0; k < 4; k++) {
            float w = __uint_as_float(e[k].y);
            ax = fmaf(w, f[k].x, ax);
            ay = fmaf(w, f[k].y, ay);
        }
    }
    for (; j < end; j += 4) {
        int idx = j + grp;
        if (idx < end) {
            uint2 e = ed[idx];
            __nv_bfloat162 v = *reinterpret_cast<const __nv_bfloat162*>(
                xb + (size_t)e.x * 16 + sub * 2);
            float2 f = __bfloat1622float2(v);
            float w = __uint_as_float(e.y);
            ax = fmaf(w, f.x, ax); ay = fmaf(w, f.y, ay);
        }
    }
    ax += __shfl_xor_sync(0xffffffffu, ax, 8);
    ay += __shfl_xor_sync(0xffffffffu, ay, 8);
    ax += __shfl_xor_sync(0xffffffffu, ax, 16);
    ay += __shfl_xor_sync(0xffffffffu, ay, 16);
    if (lane < 8) {
        float di = dis[warp];
        float2 r; r.x = -di * ax; r.y = -di * ay;
        *reinterpret_cast<float2*>(out + (size_t)warp * 16 + sub * 2) = r;
        float2 s; s.x = di * r.x; s.y = di * r.y;
        __nv_bfloat162 b = __float22bfloat162_rn(s);
        *reinterpret_cast<__nv_bfloat162*>(outb + (size_t)warp * 16 + sub * 2) = b;
    }
}

__global__ void prop_c32_p1(const __nv_bfloat16* __restrict__ xb,
                            const float* __restrict__ dis,
                            const uint2* __restrict__ ed, const int* __restrict__ rs,
                            float* __restrict__ out, __nv_bfloat16* __restrict__ outb,
                            int N) {
    int warp = (blockIdx.x * blockDim.x + threadIdx.x) >> 5;
    int lane = threadIdx.x & 31;
    if (warp >= N) return;
    int grp = lane >> 4;
    int sub = lane & 15;
    int beg = rs[warp], end = rs[warp + 1];
    float ax = 0.f, ay = 0.f;
    int j = beg;
    for (; j + 16 <= end; j += 16) {
        uint2 e[8];
#pragma unroll
        for (int k = 0; k < 8; k++) e[k] = ed[j + k * 2 + grp];
        float2 f[8];
#pragma unroll
        for (int k = 0; k < 8; k++) {
            __nv_bfloat162 v = *reinterpret_cast<const __nv_bfloat162*>(
                xb + (size_t)e[k].x * 32 + sub * 2);
            f[k] = __bfloat1622float2(v);
        }
#pragma unroll
        for (int k = 0; k < 8; k++) {
            float w = __uint_as_float(e[k].y);
            ax = fmaf(w, f[k].x, ax);
            ay = fmaf(w, f[k].y, ay);
        }
    }
    for (; j < end; j += 2) {
        int idx = j + grp;
        if (idx < end) {
            uint2 e = ed[idx];
            __nv_bfloat162 v = *reinterpret_cast<const __nv_bfloat162*>(
                xb + (size_t)e.x * 32 + sub * 2);
            float2 f = __bfloat1622float2(v);
            float w = __uint_as_float(e.y);
            ax = fmaf(w, f.x, ax); ay = fmaf(w, f.y, ay);
        }
    }
    ax += __shfl_xor_sync(0xffffffffu, ax, 16);
    ay += __shfl_xor_sync(0xffffffffu, ay, 16);
    if (lane < 16) {
        float di = dis[warp];
        float2 r; r.x = -di * ax; r.y = -di * ay;
        *reinterpret_cast<float2*>(out + (size_t)warp * 32 + sub * 2) = r;
        float2 s; s.x = di * r.x; s.y = di * r.y;
        __nv_bfloat162 b = __float22bfloat162_rn(s);
        *reinterpret_cast<__nv_bfloat162*>(outb + (size_t)warp * 32 + sub * 2) = b;
    }
}

// ===========================================================================
// Layer 2 fused pass 2 + combine 16->32
// ===========================================================================
__global__ void fused_l2(const __nv_bfloat16* __restrict__ tb,
                         const float* __restrict__ f0, const float* __restrict__ t1,
                         const float* __restrict__ dis, const float* __restrict__ W,
                         float* __restrict__ out, __nv_bfloat16* __restrict__ outb,
                         const uint2* __restrict__ ed, const int* __restrict__ rs, int N) {
    __shared__ float sW[3 * 16 * 32];
    for (int i = threadIdx.x; i < 3 * 16 * 32; i += blockDim.x) sW[i] = W[i];
    __syncthreads();
    int warp = (blockIdx.x * blockDim.x + threadIdx.x) >> 5;
    int lane = threadIdx.x & 31;
    if (warp >= N) return;
    int grp = lane >> 3;
    int sub = lane & 7;
    int beg = rs[warp], end = rs[warp + 1];
    float ax = 0.f, ay = 0.f;
    int j = beg;
    for (; j + 16 <= end; j += 16) {
        uint2 e[4];
#pragma unroll
        for (int k = 0; k < 4; k++) e[k] = ed[j + k * 4 + grp];
        float2 f[4];
#pragma unroll
        for (int k = 0; k < 4; k++) {
            __nv_bfloat162 v = *reinterpret_cast<const __nv_bfloat162*>(
                tb + (size_t)e[k].x * 16 + sub * 2);
            f[k] = __bfloat1622float2(v);
        }
#pragma unroll
        for (int k = 0; k < 4; k++) {
            float w = __uint_as_float(e[k].y);
            ax = fmaf(w, f[k].x, ax);
            ay = fmaf(w, f[k].y, ay);
        }
    }
    for (; j < end; j += 4) {
        int idx = j + grp;
        if (idx < end) {
            uint2 e = ed[idx];
            __nv_bfloat162 v = *reinterpret_cast<const __nv_bfloat162*>(
                tb + (size_t)e.x * 16 + sub * 2);
            float2 f = __bfloat1622float2(v);
            float w = __uint_as_float(e.y);
            ax = fmaf(w, f.x, ax); ay = fmaf(w, f.y, ay);
        }
    }
    ax += __shfl_xor_sync(0xffffffffu, ax, 8);
    ay += __shfl_xor_sync(0xffffffffu, ay, 8);
    ax += __shfl_xor_sync(0xffffffffu, ax, 16);
    ay += __shfl_xor_sync(0xffffffffu, ay, 16);

    float di = dis[warp];
    float t2x = -di * ax;
    float t2y = -di * ay;

    int c = lane & 15;
    float a = f0[(size_t)warp * 16 + c];
    float b = t1[(size_t)warp * 16 + c];
    float acc = 0.f;
#pragma unroll
    for (int cc = 0; cc < 16; cc++) {
        float av = __shfl_sync(0xffffffffu, a, cc);
        float bv = __shfl_sync(0xffffffffu, b, cc);
        float t2v = (cc & 1) ? __shfl_sync(0xffffffffu, t2y, cc >> 1)
                             : __shfl_sync(0xffffffffu, t2x, cc >> 1);
        float dv = 2.f * t2v - av;
        acc = fmaf(av, sW[cc * 32 + lane], acc);
        acc = fmaf(bv, sW[512 + cc * 32 + lane], acc);
        acc = fmaf(dv, sW[1024 + cc * 32 + lane], acc);
    }
    float r = fmaxf(acc, 0.f);
    out[(size_t)warp * 32 + lane] = r;
    outb[(size_t)warp * 32 + lane] = __float2bfloat16_rn(di * r);
}

// ===========================================================================
// Layer 3 fused: pass-2 gather + combine via tf32 mma.sync + head GEMM.
// Block = 512 threads = 16 warps = 16 nodes.
// A tile: 16 x 96 tf32 (stride 100 words, conflict-free fragment loads).
// Bt tile: 64 x 96 tf32 (row co = output channel).
// ===========================================================================
#define AS 100   // words per A/Bt row

__global__ void __launch_bounds__(512)
fused_l3_mma(const __nv_bfloat16* __restrict__ tb,
             const float* __restrict__ f0, const float* __restrict__ t1,
             const float* __restrict__ dis,
             const unsigned* __restrict__ wbt, const float* __restrict__ W4,
             float* __restrict__ part, float* __restrict__ zpack,
             const uint2* __restrict__ ed, const int* __restrict__ rs, int N) {
    __shared__ unsigned A_sm[16 * AS];
    __shared__ unsigned Bt_sm[64 * AS];
    __shared__ float h_sm[16 * 64];
    __shared__ float sW4[6 * 64];

    int tid = threadIdx.x;
    int wid = tid >> 5;
    int lane = tid & 31;
    int node = blockIdx.x * 16 + wid;

    // stage Bt (tf32 bits) and W4
    for (int i = tid; i < 64 * 96; i += 512) {
        int co = i / 96, k = i % 96;
        Bt_sm[co * AS + k] = wbt[i];
    }
    for (int i = tid; i < 384; i += 512) {
        int k = i / 128, rem = i % 128, ci = rem / 2, co = rem % 2;
        sW4[(k * 2 + co) * 64 + ci] = W4[i];
    }

    // ---- gather phase: t2 = -dis * P(tb) for this warp's node ----
    float di = 0.f, a = 0.f, b = 0.f, dval = 0.f;
    if (node < N) {
        int grp = lane >> 4;
        int sub = lane & 15;
        int beg = rs[node], end = rs[node + 1];
        float ax = 0.f, ay = 0.f;
        int j = beg;
        for (; j + 16 <= end; j += 16) {
            uint2 e[8];
#pragma unroll
            for (int k = 0; k < 8; k++) e[k] = ed[j + k * 2 + grp];
            float2 f[8];
#pragma unroll
            for (int k = 0; k < 8; k++) {
                __nv_bfloat162 v = *reinterpret_cast<const __nv_bfloat162*>(
                    tb + (size_t)e[k].x * 32 + sub * 2);
                f[k] = __bfloat1622float2(v);
            }
#pragma unroll
            for (int k = 0; k < 8; k++) {
                float w = __uint_as_float(e[k].y);
                ax = fmaf(w, f[k].x, ax);
                ay = fmaf(w, f[k].y, ay);
            }
        }
        for (; j < end; j += 2) {
            int idx = j + grp;
            if (idx < end) {
                uint2 e = ed[idx];
                __nv_bfloat162 v = *reinterpret_cast<const __nv_bfloat162*>(
                    tb + (size_t)e.x * 32 + sub * 2);
                float2 f = __bfloat1622float2(v);
                float w = __uint_as_float(e.y);
                ax = fmaf(w, f.x, ax); ay = fmaf(w, f.y, ay);
            }
        }
        ax += __shfl_xor_sync(0xffffffffu, ax, 16);
        ay += __shfl_xor_sync(0xffffffffu, ay, 16);
        di = dis[node];
        float t2x = -di * ax;   // channel 2*sub
        float t2y = -di * ay;   // channel 2*sub+1
        float tx = __shfl_sync(0xffffffffu, t2x, lane >> 1);
        float ty = __shfl_sync(0xffffffffu, t2y, lane >> 1);
        float t2c = (lane & 1) ? ty : tx;
        a = f0[(size_t)node * 32 + lane];
        b = t1[(size_t)node * 32 + lane];
        dval = 2.f * t2c - a;
    }
    // stage A tile in tf32 (invalid nodes contribute zeros)
    A_sm[wid * AS + lane] = to_tf32(a);
    A_sm[wid * AS + 32 + lane] = to_tf32(b);
    A_sm[wid * AS + 64 + lane] = to_tf32(dval);
    __syncthreads();

    // ---- mma: warps 0..7 each compute one m16n8 tile over K=96 (12 k8 steps) ----
    if (wid < 8) {
        int row = lane >> 2;   // 0..7
        int qc = lane & 3;     // 0..3
        float c0 = 0.f, c1 = 0.f, c2 = 0.f, c3 = 0.f;
        const unsigned* Arow0 = A_sm + row * AS;
        const unsigned* Arow1 = A_sm + (row + 8) * AS;
        const unsigned* Brow = Bt_sm + (wid * 8 + row) * AS;
#pragma unroll
        for (int kt = 0; kt < 12; kt++) {
            int k0 = kt * 8 + qc;
            unsigned a0 = Arow0[k0];
            unsigned a1 = Arow1[k0];
            unsigned a2 = Arow0[k0 + 4];
            unsigned a3 = Arow1[k0 + 4];
            unsigned b0 = Brow[k0];
            unsigned b1 = Brow[k0 + 4];
            asm volatile(
                "mma.sync.aligned.m16n8k8.row.col.f32.tf32.tf32.f32 "
                "{%0,%1,%2,%3}, {%4,%5,%6,%7}, {%8,%9}, {%0,%1,%2,%3};"
                : "+f"(c0), "+f"(c1), "+f"(c2), "+f"(c3)
                : "r"(a0), "r"(a1), "r"(a2), "r"(a3), "r"(b0), "r"(b1));
        }
        int col0 = wid * 8 + qc * 2;
        float2 v;
        v.x = fmaxf(c0, 0.f); v.y = fmaxf(c1, 0.f);
        *reinterpret_cast<float2*>(h_sm + row * 64 + col0) = v;
        v.x = fmaxf(c2, 0.f); v.y = fmaxf(c3, 0.f);
        *reinterpret_cast<float2*>(h_sm + (row + 8) * 64 + col0) = v;
    }
    __syncthreads();

    // ---- head GEMM: warp wid handles node wid of the tile ----
    if (node >= N) return;
    float h0 = h_sm[wid * 64 + lane];
    float h1 = h_sm[wid * 64 + lane + 32];
    float r[6];
#pragma unroll
    for (int m = 0; m < 6; m++) {
        const float* w = sW4 + m * 64;
        float racc = fmaf(h1, w[lane + 32], h0 * w[lane]);
#pragma unroll
        for (int off = 16; off > 0; off >>= 1)
            racc += __shfl_down_sync(0xffffffffu, racc, off);
        r[m] = racc;
    }
    if (lane == 0) {
        part[(size_t)node * 2 + 0] = r[0] - r[4];
        part[(size_t)node * 2 + 1] = r[1] - r[5];
        float4 z; z.x = di * r[2]; z.y = di * r[3]; z.z = di * r[4]; z.w = di * r[5];
        *reinterpret_cast<float4*>(zpack + (size_t)node * 4) = z;
    }
}

// ===========================================================================
// Layer-4 tail props
// ===========================================================================
__global__ void prop_csr_c4(const float* __restrict__ zs, const float* __restrict__ dis,
                            const uint2* __restrict__ ed, const int* __restrict__ rs,
                            float* __restrict__ out, int N) {
    int warp = (blockIdx.x * blockDim.x + threadIdx.x) >> 5;
    int lane = threadIdx.x & 31;
    if (warp >= N) return;
    int k = lane >> 2;
    int c = lane & 3;
    int beg = rs[warp], end = rs[warp + 1];
    float acc = 0.f;
    for (int j = beg + k; j < end; j += 8) {
        uint2 e = ed[j];
        acc = fmaf(__uint_as_float(e.y), __ldg(zs + (size_t)e.x * 4 + c), acc);
    }
#pragma unroll
    for (int off = 16; off >= 4; off >>= 1)
        acc += __shfl_down_sync(0xffffffffu, acc, off);
    if (lane < 4) {
        float di = dis[warp];
        float r = -di * acc;
        out[(size_t)warp * 4 + c] = (c < 2) ? r : di * r;
    }
}

__global__ void prop2_final_k(const float* __restrict__ t4, const float* __restrict__ part,
                              const float* __restrict__ dis,
                              const uint2* __restrict__ ed, const int* __restrict__ rs,
                              float* __restrict__ y, int N) {
    int warp = (blockIdx.x * blockDim.x + threadIdx.x) >> 5;
    int lane = threadIdx.x & 31;
    if (warp >= N) return;
    int k = lane >> 1;
    int c = lane & 1;
    int beg = rs[warp], end = rs[warp + 1];
    float acc = 0.f;
    for (int j = beg + k; j < end; j += 16) {
        uint2 e = ed[j];
        acc = fmaf(__uint_as_float(e.y), __ldg(t4 + (size_t)e.x * 4 + 2 + c), acc);
    }
#pragma unroll
    for (int off = 16; off >= 2; off >>= 1)
        acc += __shfl_down_sync(0xffffffffu, acc, off);
    if (lane < 2) {
        float w = -dis[warp] * acc;
        y[(size_t)warp * 2 + c] = part[(size_t)warp * 2 + c]
                                + t4[(size_t)warp * 4 + c] + 2.f * w;
    }
}

extern "C" void kernel_launch(void* const* d_in, const int* in_sizes, int n_in,
                              void* d_out, int out_size) {
    const float* x = (const float*)d_in[0];
    const int* edge_index = (const int*)d_in[1];
    const float* ea = (const float*)d_in[2];
    const float* W1 = (const float*)d_in[3];
    const float* W2 = (const float*)d_in[4];
    const float* W3 = (const float*)d_in[5];
    const float* W4 = (const float*)d_in[6];

    const int N = in_sizes[0];
    const int E = in_sizes[2];
    const int* src = edge_index;
    const int* dst = edge_index + E;

    float *deg, *dis, *xs, *bufA, *bufB, *t1, *t1s, *t2;
    int *cnt, *rs, *cur;
    unsigned long long* sstate;
    uint2* edges;
    __nv_bfloat16 *xb, *tb;
    unsigned* wbt;
    cudaGetSymbolAddress((void**)&deg, g_deg);
    cudaGetSymbolAddress((void**)&dis, g_dis);
    cudaGetSymbolAddress((void**)&xs, g_xs);
    cudaGetSymbolAddress((void**)&cnt, g_cnt);
    cudaGetSymbolAddress((void**)&rs, g_rs);
    cudaGetSymbolAddress((void**)&cur, g_cur);
    cudaGetSymbolAddress((void**)&sstate, g_sstate);
    cudaGetSymbolAddress((void**)&edges, g_edges);
    cudaGetSymbolAddress((void**)&bufA, g_bufA);
    cudaGetSymbolAddress((void**)&bufB, g_bufB);
    cudaGetSymbolAddress((void**)&t1, g_t1);
    cudaGetSymbolAddress((void**)&t1s, g_t1s);
    cudaGetSymbolAddress((void**)&t2, g_t2);
    cudaGetSymbolAddress((void**)&xb, g_xb);
    cudaGetSymbolAddress((void**)&tb, g_tb);
    cudaGetSymbolAddress((void**)&wbt, g_wbt);

    // ---- build CSR + dis + weight prep ----
    zero_build_k<<<cdiv(N, 256), 256>>>(deg, cnt, sstate, N);
    wprep3_k<<<cdiv(64 * 96, 256), 256>>>(W3, wbt);
    deg_hist_k<<<cdiv(cdiv(E, 4), 256), 256>>>(src, dst, ea, deg, cnt, E);
    int nb = cdiv(N, SCAN_ELEMS);
    scan_lookback_k<<<nb, SCAN_TPB>>>(cnt, sstate, rs, cur, N);
    scatter_k<<<cdiv(E, 256), 256>>>(src, dst, ea, cur, edges, E);
    dis_k<<<cdiv(N, 256), 256>>>(deg, x, dis, xs, N);

    const int WPB = 256;
    int grid_n = cdiv((long long)N * 32, WPB);

    // ---- layer 1 ----
    prop_c1_p1<<<grid_n, WPB>>>(xs, dis, edges, rs, t1, t1s, N);
    fused_l1<<<grid_n, WPB>>>(t1s, x, t1, dis, W1, bufA, xb, edges, rs, N);

    // ---- layer 2 ----
    prop_c16_p1<<<grid_n, WPB>>>(xb, dis, edges, rs, t1, tb, N);
    fused_l2<<<grid_n, WPB>>>(tb, bufA, t1, dis, W2, bufB, xb, edges, rs, N);

    // ---- layer 3 (tf32 mma combine) + head ----
    prop_c32_p1<<<grid_n, WPB>>>(xb, dis, edges, rs, t1, tb, N);
    fused_l3_mma<<<cdiv(N, 16), 512>>>(tb, bufB, t1, dis, wbt, W4,
                                       bufA, t2, edges, rs, N);

    // ---- layer 4 tail ----
    prop_csr_c4<<<grid_n, WPB>>>(t2, dis, edges, rs, bufB, N);
    prop2_final_k<<<grid_n, WPB>>>(bufB, bufA, dis, edges, rs, (float*)d_out, N);
}

// round 14
// speedup vs baseline: 1.3159x; 1.0495x over previous
#include <cuda_runtime.h>
#include <cuda_bf16.h>
#include <cstdint>

#define NMAX 100000
#define EMAX 3200000

// Scratch (device globals: allocation is forbidden).
__device__ float g_deg[NMAX];
__device__ float g_dis[NMAX];
__device__ float g_xs[NMAX];
__device__ int   g_cnt[NMAX];
__device__ int   g_rs[NMAX + 1];
__device__ int   g_cur[NMAX];
__device__ unsigned long long g_sstate[128];
__device__ uint2 g_edges[EMAX];         // {src, ea} sorted by dst
__device__ float g_bufA[NMAX * 64];     // layer-1 out (N*16) -> later part (N*2)
__device__ float g_bufB[NMAX * 64];     // layer-2 out (N*32) -> later zprop (N*4)
__device__ float g_t1[NMAX * 64];
__device__ float g_t1s[NMAX];
__device__ float g_t2[NMAX * 64];       // zpack (N*4)
__device__ __nv_bfloat16 g_xb[NMAX * 32];   // bf16 shadow (dis-scaled)
__device__ __nv_bfloat16 g_tb[NMAX * 32];   // bf16 shadow of t1 (dis-scaled)
__device__ unsigned g_wbt3[64 * 96];        // W3 as Bt[co][k], tf32 bits
__device__ unsigned g_wbt2[32 * 48];        // W2 as Bt[co][k], tf32 bits

static inline int cdiv(long long a, int b) { return (int)((a + b - 1) / b); }

__device__ __forceinline__ unsigned to_tf32(float v) {
    unsigned u;
    asm("cvt.rna.tf32.f32 %0, %1;" : "=r"(u) : "f"(v));
    return u;
}

// ===========================================================================
// Build phase
// ===========================================================================
__global__ void zero_build_k(float* deg, int* cnt, unsigned long long* sstate, int n) {
    int i = blockIdx.x * blockDim.x + threadIdx.x;
    if (i < n) { deg[i] = 0.f; cnt[i] = 0; }
    if (i < 128) sstate[i] = 0ULL;
}

__global__ void deg_hist_k(const int* __restrict__ src, const int* __restrict__ dst,
                           const float* __restrict__ ea,
                           float* __restrict__ deg, int* __restrict__ cnt, int E) {
    int base = (blockIdx.x * blockDim.x + threadIdx.x) * 4;
    if (base + 3 < E) {
        int4 s = *reinterpret_cast<const int4*>(src + base);
        int4 d = *reinterpret_cast<const int4*>(dst + base);
        float4 w = *reinterpret_cast<const float4*>(ea + base);
        atomicAdd(&deg[s.x], w.x);
        atomicAdd(&deg[s.y], w.y);
        atomicAdd(&deg[s.z], w.z);
        atomicAdd(&deg[s.w], w.w);
        atomicAdd(&cnt[d.x], 1);
        atomicAdd(&cnt[d.y], 1);
        atomicAdd(&cnt[d.z], 1);
        atomicAdd(&cnt[d.w], 1);
    } else {
        for (int e = base; e < E; e++) {
            atomicAdd(&deg[src[e]], ea[e]);
            atomicAdd(&cnt[dst[e]], 1);
        }
    }
}

__global__ void dis_k(const float* __restrict__ deg, const float* __restrict__ x,
                      float* __restrict__ dis, float* __restrict__ xs, int n) {
    int i = blockIdx.x * blockDim.x + threadIdx.x;
    if (i >= n) return;
    float d = deg[i];
    float r = d > 0.f ? rsqrtf(d) : 0.f;
    dis[i] = r;
    xs[i] = r * x[i];
}

#define SCAN_TPB 256
#define SCAN_ELEMS 1024

__global__ void scan_lookback_k(const int* __restrict__ cnt,
                                unsigned long long* __restrict__ sstate,
                                int* __restrict__ rs, int* __restrict__ cur, int n) {
    int b = blockIdx.x;
    int base = b * SCAN_ELEMS + threadIdx.x * 4;
    int c0 = 0, c1 = 0, c2 = 0, c3 = 0;
    if (base + 3 < n) {
        int4 v = *reinterpret_cast<const int4*>(cnt + base);
        c0 = v.x; c1 = v.y; c2 = v.z; c3 = v.w;
    } else {
        if (base + 0 < n) c0 = cnt[base + 0];
        if (base + 1 < n) c1 = cnt[base + 1];
        if (base + 2 < n) c2 = cnt[base + 2];
        if (base + 3 < n) c3 = cnt[base + 3];
    }
    int ts = c0 + c1 + c2 + c3;
    int lane = threadIdx.x & 31, wid = threadIdx.x >> 5;
    int inc = ts;
#pragma unroll
    for (int o = 1; o < 32; o <<= 1) {
        int v = __shfl_up_sync(0xffffffffu, inc, o);
        if (lane >= o) inc += v;
    }
    __shared__ int wsum[SCAN_TPB / 32];
    __shared__ int woff[SCAN_TPB / 32];
    __shared__ int s_base;
    __shared__ int s_total;
    if (lane == 31) wsum[wid] = inc;
    __syncthreads();
    if (threadIdx.x == 0) {
        int r = 0;
#pragma unroll
        for (int w = 0; w < SCAN_TPB / 32; w++) { woff[w] = r; r += wsum[w]; }
        s_total = r;
        atomicExch(&sstate[b], (1ULL << 62) | (unsigned)r);
        int excl = 0;
        for (int p = b - 1; p >= 0; ) {
            unsigned long long s;
            do { s = atomicAdd(&sstate[p], 0ULL); } while ((s >> 62) == 0);
            excl += (int)(unsigned)s;
            if ((s >> 62) == 2ULL) break;
            p--;
        }
        atomicExch(&sstate[b], (2ULL << 62) | (unsigned)(excl + r));
        s_base = excl;
    }
    __syncthreads();
    int r = s_base + (inc - ts) + woff[wid];
    if (base + 0 < n) { rs[base + 0] = r; cur[base + 0] = r; r += c0; }
    if (base + 1 < n) { rs[base + 1] = r; cur[base + 1] = r; r += c1; }
    if (base + 2 < n) { rs[base + 2] = r; cur[base + 2] = r; r += c2; }
    if (base + 3 < n) { rs[base + 3] = r; cur[base + 3] = r; r += c3; }
    if (b == gridDim.x - 1 && threadIdx.x == 0) rs[n] = s_base + s_total;
}

// 1 edge/thread (measured best)
__global__ void scatter_k(const int* __restrict__ src, const int* __restrict__ dst,
                          const float* __restrict__ ea,
                          int* __restrict__ cur, uint2* __restrict__ ed, int E) {
    int e = blockIdx.x * blockDim.x + threadIdx.x;
    if (e >= E) return;
    int d = dst[e];
    int slot = atomicAdd(&cur[d], 1);
    ed[slot] = make_uint2((unsigned)src[e], __float_as_uint(ea[e]));
}

// W3 -> Bt3[co][k] tf32 bits, k in 0..95 over [W3_0; W3_1; W3_2]
// W2 -> Bt2[co][k] tf32 bits, k in 0..47 over [W2_0; W2_1; W2_2]
__global__ void wprep_k(const float* __restrict__ W3, const float* __restrict__ W2,
                        unsigned* __restrict__ wbt3, unsigned* __restrict__ wbt2) {
    int i = blockIdx.x * blockDim.x + threadIdx.x;
    if (i < 64 * 96) {
        int co = i / 96, k = i % 96;
        wbt3[i] = to_tf32(W3[(k >> 5) * 2048 + (k & 31) * 64 + co]);
    }
    if (i < 32 * 48) {
        int co = i / 48, k = i % 48;
        wbt2[i] = to_tf32(W2[(k >> 4) * 512 + (k & 15) * 32 + co]);
    }
}

// ===========================================================================
// Layer 1
// ===========================================================================
__global__ void prop_c1_p1(const float* __restrict__ xs, const float* __restrict__ dis,
                           const uint2* __restrict__ ed, const int* __restrict__ rs,
                           float* __restrict__ out, float* __restrict__ outs, int N) {
    int warp = (blockIdx.x * blockDim.x + threadIdx.x) >> 5;
    int lane = threadIdx.x & 31;
    if (warp >= N) return;
    int beg = rs[warp], end = rs[warp + 1];
    float acc = 0.f;
    for (int j = beg + lane; j < end; j += 32) {
        uint2 e = ed[j];
        acc += __uint_as_float(e.y) * __ldg(xs + e.x);
    }
#pragma unroll
    for (int off = 16; off > 0; off >>= 1)
        acc += __shfl_down_sync(0xffffffffu, acc, off);
    if (lane == 0) {
        float di = dis[warp];
        float r = -di * acc;
        out[warp] = r;
        outs[warp] = di * r;
    }
}

__global__ void fused_l1(const float* __restrict__ t1s, const float* __restrict__ x,
                         const float* __restrict__ t1, const float* __restrict__ dis,
                         const float* __restrict__ W,
                         float* __restrict__ out, __nv_bfloat16* __restrict__ outb,
                         const uint2* __restrict__ ed, const int* __restrict__ rs, int N) {
    __shared__ float sW[48];
    if (threadIdx.x < 48) sW[threadIdx.x] = W[threadIdx.x];
    __syncthreads();
    int warp = (blockIdx.x * blockDim.x + threadIdx.x) >> 5;
    int lane = threadIdx.x & 31;
    if (warp >= N) return;
    int beg = rs[warp], end = rs[warp + 1];
    float acc = 0.f;
    for (int j = beg + lane; j < end; j += 32) {
        uint2 e = ed[j];
        acc += __uint_as_float(e.y) * __ldg(t1s + e.x);
    }
#pragma unroll
    for (int off = 16; off > 0; off >>= 1)
        acc += __shfl_xor_sync(0xffffffffu, acc, off);
    float di = dis[warp];
    float t2v = -di * acc;
    float a = x[warp];
    float b = t1[warp];
    if (lane < 16) {
        float d = 2.f * t2v - a;
        float r = fmaxf(a * sW[lane] + b * sW[16 + lane] + d * sW[32 + lane], 0.f);
        out[(size_t)warp * 16 + lane] = r;
        outb[(size_t)warp * 16 + lane] = __float2bfloat16_rn(di * r);
    }
}

// ===========================================================================
// Layer 2/3 pass-1 props
// ===========================================================================
__global__ void prop_c16_p1(const __nv_bfloat16* __restrict__ xb,
                            const float* __restrict__ dis,
                            const uint2* __restrict__ ed, const int* __restrict__ rs,
                            float* __restrict__ out, __nv_bfloat16* __restrict__ outb,
                            int N) {
    int warp = (blockIdx.x * blockDim.x + threadIdx.x) >> 5;
    int lane = threadIdx.x & 31;
    if (warp >= N) return;
    int grp = lane >> 3;
    int sub = lane & 7;
    int beg = rs[warp], end = rs[warp + 1];
    float ax = 0.f, ay = 0.f;
    int j = beg;
    for (; j + 16 <= end; j += 16) {
        uint2 e[4];
#pragma unroll
        for (int k = 0; k < 4; k++) e[k] = ed[j + k * 4 + grp];
        float2 f[4];
#pragma unroll
        for (int k = 0; k < 4; k++) {
            __nv_bfloat162 v = *reinterpret_cast<const __nv_bfloat162*>(
                xb + (size_t)e[k].x * 16 + sub * 2);
            f[k] = __bfloat1622float2(v);
        }
#pragma unroll
        for (int k = 0; k < 4; k++) {
            float w = __uint_as_float(e[k].y);
            ax = fmaf(w, f[k].x, ax);
            ay = fmaf(w, f[k].y, ay);
        }
    }
    for (; j < end; j += 4) {
        int idx = j + grp;
        if (idx < end) {
            uint2 e = ed[idx];
            __nv_bfloat162 v = *reinterpret_cast<const __nv_bfloat162*>(
                xb + (size_t)e.x * 16 + sub * 2);
            float2 f = __bfloat1622float2(v);
            float w = __uint_as_float(e.y);
            ax = fmaf(w, f.x, ax); ay = fmaf(w, f.y, ay);
        }
    }
    ax += __shfl_xor_sync(0xffffffffu, ax, 8);
    ay += __shfl_xor_sync(0xffffffffu, ay, 8);
    ax += __shfl_xor_sync(0xffffffffu, ax, 16);
    ay += __shfl_xor_sync(0xffffffffu, ay, 16);
    if (lane < 8) {
        float di = dis[warp];
        float2 r; r.x = -di * ax; r.y = -di * ay;
        *reinterpret_cast<float2*>(out + (size_t)warp * 16 + sub * 2) = r;
        float2 s; s.x = di * r.x; s.y = di * r.y;
        __nv_bfloat162 b = __float22bfloat162_rn(s);
        *reinterpret_cast<__nv_bfloat162*>(outb + (size_t)warp * 16 + sub * 2) = b;
    }
}

__global__ void prop_c32_p1(const __nv_bfloat16* __restrict__ xb,
                            const float* __restrict__ dis,
                            const uint2* __restrict__ ed, const int* __restrict__ rs,
                            float* __restrict__ out, __nv_bfloat16* __restrict__ outb,
                            int N) {
    int warp = (blockIdx.x * blockDim.x + threadIdx.x) >> 5;
    int lane = threadIdx.x & 31;
    if (warp >= N) return;
    int grp = lane >> 4;
    int sub = lane & 15;
    int beg = rs[warp], end = rs[warp + 1];
    float ax = 0.f, ay = 0.f;
    int j = beg;
    for (; j + 16 <= end; j += 16) {
        uint2 e[8];
#pragma unroll
        for (int k = 0; k < 8; k++) e[k] = ed[j + k * 2 + grp];
        float2 f[8];
#pragma unroll
        for (int k = 0; k < 8; k++) {
            __nv_bfloat162 v = *reinterpret_cast<const __nv_bfloat162*>(
                xb + (size_t)e[k].x * 32 + sub * 2);
            f[k] = __bfloat1622float2(v);
        }
#pragma unroll
        for (int k = 0; k < 8; k++) {
            float w = __uint_as_float(e[k].y);
            ax = fmaf(w, f[k].x, ax);
            ay = fmaf(w, f[k].y, ay);
        }
    }
    for (; j < end; j += 2) {
        int idx = j + grp;
        if (idx < end) {
            uint2 e = ed[idx];
            __nv_bfloat162 v = *reinterpret_cast<const __nv_bfloat162*>(
                xb + (size_t)e.x * 32 + sub * 2);
            float2 f = __bfloat1622float2(v);
            float w = __uint_as_float(e.y);
            ax = fmaf(w, f.x, ax); ay = fmaf(w, f.y, ay);
        }
    }
    ax += __shfl_xor_sync(0xffffffffu, ax, 16);
    ay += __shfl_xor_sync(0xffffffffu, ay, 16);
    if (lane < 16) {
        float di = dis[warp];
        float2 r; r.x = -di * ax; r.y = -di * ay;
        *reinterpret_cast<float2*>(out + (size_t)warp * 32 + sub * 2) = r;
        float2 s; s.x = di * r.x; s.y = di * r.y;
        __nv_bfloat162 b = __float22bfloat162_rn(s);
        *reinterpret_cast<__nv_bfloat162*>(outb + (size_t)warp * 32 + sub * 2) = b;
    }
}

// ===========================================================================
// Layer 2 fused: pass-2 gather + combine 16->32 via tf32 mma.
// Block = 512 threads = 16 warps = 16 nodes. A: 16x48 tf32, Bt: 32x48.
// ===========================================================================
#define AS2 52

__global__ void __launch_bounds__(512)
fused_l2_mma(const __nv_bfloat16* __restrict__ tb,
             const float* __restrict__ f0, const float* __restrict__ t1,
             const float* __restrict__ dis, const unsigned* __restrict__ wbt2,
             float* __restrict__ out, __nv_bfloat16* __restrict__ outb,
             const uint2* __restrict__ ed, const int* __restrict__ rs, int N) {
    __shared__ unsigned A_sm[16 * AS2];
    __shared__ unsigned Bt_sm[32 * AS2];
    __shared__ float h_sm[16 * 32];
    __shared__ float dis_sm[16];

    int tid = threadIdx.x;
    int wid = tid >> 5;
    int lane = tid & 31;
    int node = blockIdx.x * 16 + wid;

    for (int i = tid; i < 32 * 48; i += 512) {
        int co = i / 48, k = i % 48;
        Bt_sm[co * AS2 + k] = wbt2[i];
    }

    // ---- gather: t2 channels for this node (c16 layout) ----
    float di = 0.f;
    float t2x = 0.f, t2y = 0.f;
    if (node < N) {
        int grp = lane >> 3;
        int sub = lane & 7;
        int beg = rs[node], end = rs[node + 1];
        float ax = 0.f, ay = 0.f;
        int j = beg;
        for (; j + 16 <= end; j += 16) {
            uint2 e[4];
#pragma unroll
            for (int k = 0; k < 4; k++) e[k] = ed[j + k * 4 + grp];
            float2 f[4];
#pragma unroll
            for (int k = 0; k < 4; k++) {
                __nv_bfloat162 v = *reinterpret_cast<const __nv_bfloat162*>(
                    tb + (size_t)e[k].x * 16 + sub * 2);
                f[k] = __bfloat1622float2(v);
            }
#pragma unroll
            for (int k = 0; k < 4; k++) {
                float w = __uint_as_float(e[k].y);
                ax = fmaf(w, f[k].x, ax);
                ay = fmaf(w, f[k].y, ay);
            }
        }
        for (; j < end; j += 4) {
            int idx = j + grp;
            if (idx < end) {
                uint2 e = ed[idx];
                __nv_bfloat162 v = *reinterpret_cast<const __nv_bfloat162*>(
                    tb + (size_t)e.x * 16 + sub * 2);
                float2 f = __bfloat1622float2(v);
                float w = __uint_as_float(e.y);
                ax = fmaf(w, f.x, ax); ay = fmaf(w, f.y, ay);
            }
        }
        ax += __shfl_xor_sync(0xffffffffu, ax, 8);
        ay += __shfl_xor_sync(0xffffffffu, ay, 8);
        ax += __shfl_xor_sync(0xffffffffu, ax, 16);
        ay += __shfl_xor_sync(0xffffffffu, ay, 16);
        di = dis[node];
        t2x = -di * ax;   // channel 2*sub
        t2y = -di * ay;   // channel 2*sub+1
    }
    if (lane == 0) dis_sm[wid] = di;

    // stage A row: [a(16) | b(16) | d(16)]
    {
        int c = lane & 15;
        float a = 0.f, b = 0.f, dval = 0.f;
        if (node < N) {
            a = f0[(size_t)node * 16 + c];
            b = t1[(size_t)node * 16 + c];
            float tx = __shfl_sync(0xffffffffu, t2x, c >> 1);
            float ty = __shfl_sync(0xffffffffu, t2y, c >> 1);
            float t2c = (c & 1) ? ty : tx;
            dval = 2.f * t2c - a;
        }
        if (lane < 16) {
            A_sm[wid * AS2 + c] = to_tf32(a);
            A_sm[wid * AS2 + 16 + c] = to_tf32(b);
            A_sm[wid * AS2 + 32 + c] = to_tf32(dval);
        }
    }
    __syncthreads();

    // ---- mma: warps 0..3 each compute one m16n8 tile over K=48 (6 k8 steps) ----
    if (wid < 4) {
        int row = lane >> 2;
        int qc = lane & 3;
        float c0 = 0.f, c1 = 0.f, c2 = 0.f, c3 = 0.f;
        const unsigned* Arow0 = A_sm + row * AS2;
        const unsigned* Arow1 = A_sm + (row + 8) * AS2;
        const unsigned* Brow = Bt_sm + (wid * 8 + row) * AS2;
#pragma unroll
        for (int kt = 0; kt < 6; kt++) {
            int k0 = kt * 8 + qc;
            unsigned a0 = Arow0[k0];
            unsigned a1 = Arow1[k0];
            unsigned a2 = Arow0[k0 + 4];
            unsigned a3 = Arow1[k0 + 4];
            unsigned b0 = Brow[k0];
            unsigned b1 = Brow[k0 + 4];
            asm volatile(
                "mma.sync.aligned.m16n8k8.row.col.f32.tf32.tf32.f32 "
                "{%0,%1,%2,%3}, {%4,%5,%6,%7}, {%8,%9}, {%0,%1,%2,%3};"
                : "+f"(c0), "+f"(c1), "+f"(c2), "+f"(c3)
                : "r"(a0), "r"(a1), "r"(a2), "r"(a3), "r"(b0), "r"(b1));
        }
        int col0 = wid * 8 + qc * 2;
        float2 v;
        v.x = fmaxf(c0, 0.f); v.y = fmaxf(c1, 0.f);
        *reinterpret_cast<float2*>(h_sm + row * 32 + col0) = v;
        v.x = fmaxf(c2, 0.f); v.y = fmaxf(c3, 0.f);
        *reinterpret_cast<float2*>(h_sm + (row + 8) * 32 + col0) = v;
    }
    __syncthreads();

    // ---- write out + bf16 shadow: warp wid -> node wid ----
    if (node >= N) return;
    float dw = dis_sm[wid];
    float h = h_sm[wid * 32 + lane];
    out[(size_t)node * 32 + lane] = h;
    outb[(size_t)node * 32 + lane] = __float2bfloat16_rn(dw * h);
}

// ===========================================================================
// Layer 3 fused: pass-2 gather + combine via tf32 mma + head GEMM (R13).
// ===========================================================================
#define AS 100

__global__ void __launch_bounds__(512)
fused_l3_mma(const __nv_bfloat16* __restrict__ tb,
             const float* __restrict__ f0, const float* __restrict__ t1,
             const float* __restrict__ dis,
             const unsigned* __restrict__ wbt, const float* __restrict__ W4,
             float* __restrict__ part, float* __restrict__ zpack,
             const uint2* __restrict__ ed, const int* __restrict__ rs, int N) {
    __shared__ unsigned A_sm[16 * AS];
    __shared__ unsigned Bt_sm[64 * AS];
    __shared__ float h_sm[16 * 64];
    __shared__ float sW4[6 * 64];

    int tid = threadIdx.x;
    int wid = tid >> 5;
    int lane = tid & 31;
    int node = blockIdx.x * 16 + wid;

    for (int i = tid; i < 64 * 96; i += 512) {
        int co = i / 96, k = i % 96;
        Bt_sm[co * AS + k] = wbt[i];
    }
    for (int i = tid; i < 384; i += 512) {
        int k = i / 128, rem = i % 128, ci = rem / 2, co = rem % 2;
        sW4[(k * 2 + co) * 64 + ci] = W4[i];
    }

    float di = 0.f, a = 0.f, b = 0.f, dval = 0.f;
    if (node < N) {
        int grp = lane >> 4;
        int sub = lane & 15;
        int beg = rs[node], end = rs[node + 1];
        float ax = 0.f, ay = 0.f;
        int j = beg;
        for (; j + 16 <= end; j += 16) {
            uint2 e[8];
#pragma unroll
            for (int k = 0; k < 8; k++) e[k] = ed[j + k * 2 + grp];
            float2 f[8];
#pragma unroll
            for (int k = 0; k < 8; k++) {
                __nv_bfloat162 v = *reinterpret_cast<const __nv_bfloat162*>(
                    tb + (size_t)e[k].x * 32 + sub * 2);
                f[k] = __bfloat1622float2(v);
            }
#pragma unroll
            for (int k = 0; k < 8; k++) {
                float w = __uint_as_float(e[k].y);
                ax = fmaf(w, f[k].x, ax);
                ay = fmaf(w, f[k].y, ay);
            }
        }
        for (; j < end; j += 2) {
            int idx = j + grp;
            if (idx < end) {
                uint2 e = ed[idx];
                __nv_bfloat162 v = *reinterpret_cast<const __nv_bfloat162*>(
                    tb + (size_t)e.x * 32 + sub * 2);
                float2 f = __bfloat1622float2(v);
                float w = __uint_as_float(e.y);
                ax = fmaf(w, f.x, ax); ay = fmaf(w, f.y, ay);
            }
        }
        ax += __shfl_xor_sync(0xffffffffu, ax, 16);
        ay += __shfl_xor_sync(0xffffffffu, ay, 16);
        di = dis[node];
        float t2x = -di * ax;
        float t2y = -di * ay;
        float tx = __shfl_sync(0xffffffffu, t2x, lane >> 1);
        float ty = __shfl_sync(0xffffffffu, t2y, lane >> 1);
        float t2c = (lane & 1) ? ty : tx;
        a = f0[(size_t)node * 32 + lane];
        b = t1[(size_t)node * 32 + lane];
        dval = 2.f * t2c - a;
    }
    A_sm[wid * AS + lane] = to_tf32(a);
    A_sm[wid * AS + 32 + lane] = to_tf32(b);
    A_sm[wid * AS + 64 + lane] = to_tf32(dval);
    __syncthreads();

    if (wid < 8) {
        int row = lane >> 2;
        int qc = lane & 3;
        float c0 = 0.f, c1 = 0.f, c2 = 0.f, c3 = 0.f;
        const unsigned* Arow0 = A_sm + row * AS;
        const unsigned* Arow1 = A_sm + (row + 8) * AS;
        const unsigned* Brow = Bt_sm + (wid * 8 + row) * AS;
#pragma unroll
        for (int kt = 0; kt < 12; kt++) {
            int k0 = kt * 8 + qc;
            unsigned a0 = Arow0[k0];
            unsigned a1 = Arow1[k0];
            unsigned a2 = Arow0[k0 + 4];
            unsigned a3 = Arow1[k0 + 4];
            unsigned b0 = Brow[k0];
            unsigned b1 = Brow[k0 + 4];
            asm volatile(
                "mma.sync.aligned.m16n8k8.row.col.f32.tf32.tf32.f32 "
                "{%0,%1,%2,%3}, {%4,%5,%6,%7}, {%8,%9}, {%0,%1,%2,%3};"
                : "+f"(c0), "+f"(c1), "+f"(c2), "+f"(c3)
                : "r"(a0), "r"(a1), "r"(a2), "r"(a3), "r"(b0), "r"(b1));
        }
        int col0 = wid * 8 + qc * 2;
        float2 v;
        v.x = fmaxf(c0, 0.f); v.y = fmaxf(c1, 0.f);
        *reinterpret_cast<float2*>(h_sm + row * 64 + col0) = v;
        v.x = fmaxf(c2, 0.f); v.y = fmaxf(c3, 0.f);
        *reinterpret_cast<float2*>(h_sm + (row + 8) * 64 + col0) = v;
    }
    __syncthreads();

    if (node >= N) return;
    float h0 = h_sm[wid * 64 + lane];
    float h1 = h_sm[wid * 64 + lane + 32];
    float r[6];
#pragma unroll
    for (int m = 0; m < 6; m++) {
        const float* w = sW4 + m * 64;
        float racc = fmaf(h1, w[lane + 32], h0 * w[lane]);
#pragma unroll
        for (int off = 16; off > 0; off >>= 1)
            racc += __shfl_down_sync(0xffffffffu, racc, off);
        r[m] = racc;
    }
    if (lane == 0) {
        part[(size_t)node * 2 + 0] = r[0] - r[4];
        part[(size_t)node * 2 + 1] = r[1] - r[5];
        float4 z; z.x = di * r[2]; z.y = di * r[3]; z.z = di * r[4]; z.w = di * r[5];
        *reinterpret_cast<float4*>(zpack + (size_t)node * 4) = z;
    }
}

// ===========================================================================
// Layer-4 tail props
// ===========================================================================
__global__ void prop_csr_c4(const float* __restrict__ zs, const float* __restrict__ dis,
                            const uint2* __restrict__ ed, const int* __restrict__ rs,
                            float* __restrict__ out, int N) {
    int warp = (blockIdx.x * blockDim.x + threadIdx.x) >> 5;
    int lane = threadIdx.x & 31;
    if (warp >= N) return;
    int k = lane >> 2;
    int c = lane & 3;
    int beg = rs[warp], end = rs[warp + 1];
    float acc = 0.f;
    for (int j = beg + k; j < end; j += 8) {
        uint2 e = ed[j];
        acc = fmaf(__uint_as_float(e.y), __ldg(zs + (size_t)e.x * 4 + c), acc);
    }
#pragma unroll
    for (int off = 16; off >= 4; off >>= 1)
        acc += __shfl_down_sync(0xffffffffu, acc, off);
    if (lane < 4) {
        float di = dis[warp];
        float r = -di * acc;
        out[(size_t)warp * 4 + c] = (c < 2) ? r : di * r;
    }
}

__global__ void prop2_final_k(const float* __restrict__ t4, const float* __restrict__ part,
                              const float* __restrict__ dis,
                              const uint2* __restrict__ ed, const int* __restrict__ rs,
                              float* __restrict__ y, int N) {
    int warp = (blockIdx.x * blockDim.x + threadIdx.x) >> 5;
    int lane = threadIdx.x & 31;
    if (warp >= N) return;
    int k = lane >> 1;
    int c = lane & 1;
    int beg = rs[warp], end = rs[warp + 1];
    float acc = 0.f;
    for (int j = beg + k; j < end; j += 16) {
        uint2 e = ed[j];
        acc = fmaf(__uint_as_float(e.y), __ldg(t4 + (size_t)e.x * 4 + 2 + c), acc);
    }
#pragma unroll
    for (int off = 16; off >= 2; off >>= 1)
        acc += __shfl_down_sync(0xffffffffu, acc, off);
    if (lane < 2) {
        float w = -dis[warp] * acc;
        y[(size_t)warp * 2 + c] = part[(size_t)warp * 2 + c]
                                + t4[(size_t)warp * 4 + c] + 2.f * w;
    }
}

extern "C" void kernel_launch(void* const* d_in, const int* in_sizes, int n_in,
                              void* d_out, int out_size) {
    const float* x = (const float*)d_in[0];
    const int* edge_index = (const int*)d_in[1];
    const float* ea = (const float*)d_in[2];
    const float* W1 = (const float*)d_in[3];
    const float* W2 = (const float*)d_in[4];
    const float* W3 = (const float*)d_in[5];
    const float* W4 = (const float*)d_in[6];

    const int N = in_sizes[0];
    const int E = in_sizes[2];
    const int* src = edge_index;
    const int* dst = edge_index + E;

    float *deg, *dis, *xs, *bufA, *bufB, *t1, *t1s, *t2;
    int *cnt, *rs, *cur;
    unsigned long long* sstate;
    uint2* edges;
    __nv_bfloat16 *xb, *tb;
    unsigned *wbt3, *wbt2;
    cudaGetSymbolAddress((void**)&deg, g_deg);
    cudaGetSymbolAddress((void**)&dis, g_dis);
    cudaGetSymbolAddress((void**)&xs, g_xs);
    cudaGetSymbolAddress((void**)&cnt, g_cnt);
    cudaGetSymbolAddress((void**)&rs, g_rs);
    cudaGetSymbolAddress((void**)&cur, g_cur);
    cudaGetSymbolAddress((void**)&sstate, g_sstate);
    cudaGetSymbolAddress((void**)&edges, g_edges);
    cudaGetSymbolAddress((void**)&bufA, g_bufA);
    cudaGetSymbolAddress((void**)&bufB, g_bufB);
    cudaGetSymbolAddress((void**)&t1, g_t1);
    cudaGetSymbolAddress((void**)&t1s, g_t1s);
    cudaGetSymbolAddress((void**)&t2, g_t2);
    cudaGetSymbolAddress((void**)&xb, g_xb);
    cudaGetSymbolAddress((void**)&tb, g_tb);
    cudaGetSymbolAddress((void**)&wbt3, g_wbt3);
    cudaGetSymbolAddress((void**)&wbt2, g_wbt2);

    // ---- build CSR + dis + weight prep ----
    zero_build_k<<<cdiv(N, 256), 256>>>(deg, cnt, sstate, N);
    wprep_k<<<cdiv(64 * 96, 256), 256>>>(W3, W2, wbt3, wbt2);
    deg_hist_k<<<cdiv(cdiv(E, 4), 256), 256>>>(src, dst, ea, deg, cnt, E);
    int nb = cdiv(N, SCAN_ELEMS);
    scan_lookback_k<<<nb, SCAN_TPB>>>(cnt, sstate, rs, cur, N);
    scatter_k<<<cdiv(E, 256), 256>>>(src, dst, ea, cur, edges, E);
    dis_k<<<cdiv(N, 256), 256>>>(deg, x, dis, xs, N);

    const int WPB = 256;
    int grid_n = cdiv((long long)N * 32, WPB);

    // ---- layer 1 ----
    prop_c1_p1<<<grid_n, WPB>>>(xs, dis, edges, rs, t1, t1s, N);
    fused_l1<<<grid_n, WPB>>>(t1s, x, t1, dis, W1, bufA, xb, edges, rs, N);

    // ---- layer 2 (tf32 mma combine) ----
    prop_c16_p1<<<grid_n, WPB>>>(xb, dis, edges, rs, t1, tb, N);
    fused_l2_mma<<<cdiv(N, 16), 512>>>(tb, bufA, t1, dis, wbt2, bufB, xb, edges, rs, N);

    // ---- layer 3 (tf32 mma combine) + head ----
    prop_c32_p1<<<grid_n, WPB>>>(xb, dis, edges, rs, t1, tb, N);
    fused_l3_mma<<<cdiv(N, 16), 512>>>(tb, bufB, t1, dis, wbt3, W4,
                                       bufA, t2, edges, rs, N);

    // ---- layer 4 tail ----
    prop_csr_c4<<<grid_n, WPB>>>(t2, dis, edges, rs, bufB, N);
    prop2_final_k<<<grid_n, WPB>>>(bufB, bufA, dis, edges, rs, (float*)d_out, N);
}